// round 14
// baseline (speedup 1.0000x reference)
#include <cuda_runtime.h>
#include <cuda_fp16.h>
#include <cstdint>

typedef unsigned long long u64;
typedef unsigned u32;

// Problem constants
constexpr int B_ = 8;
constexpr int D_ = 128;
constexpr int S_ = 1024;
constexpr int C_ = 512;
constexpr int K_ = 16384;
constexpr float INV_TAU = 5.0f;
constexpr float MARGIN = 3e-3f;

// Output layout (flattened concatenation, float32)
constexpr size_t OG = 0;
constexpr size_t TG = (size_t)B_ * (K_ + 1);
constexpr size_t OD = TG + B_;
constexpr size_t TD = OD + (size_t)B_ * (K_ + 1) * S_;

// Scratch (device globals; no allocation allowed)
__device__ float g_dqt[B_ * S_ * D_];   // normalized d_q, transposed [b][s][d]
__device__ float g_dkt[B_ * S_ * D_];   // normalized d_k, transposed [b][s][d]
__device__ float g_fkinv[B_ * S_];      // 1/||feat_k[:,i]||
__device__ u32   g_top4[B_ * S_ * 32];  // per (col, itile): top-4 packed keys

// fp16 transposed raw features: [b][s][c]
__device__ __half g_fkh[B_ * S_ * C_];
__device__ __half g_fqh[B_ * S_ * C_];

// fp16 row-major tiles for negd: [tile][row(128)][d(128)]
__device__ uint4 g_qt4[128 * 2048];     // queue_d
__device__ uint4 g_bt4[64 * 2048];      // gathered d_q (8b x 8 z-tiles of 128)

// ---------- helpers ----------
__device__ __forceinline__ unsigned ford(float f) {
    unsigned u = __float_as_uint(f);
    return (u & 0x80000000u) ? ~u : (u | 0x80000000u);
}
__device__ __forceinline__ float unford(unsigned x) {
    unsigned u = (x & 0x80000000u) ? (x & 0x7FFFFFFFu) : ~x;
    return __uint_as_float(u);
}

// packed key: [22b truncated ford(value)][10b (1023 - index)]
__device__ __forceinline__ u32 mkkey(float v, unsigned ig) {
    return (ford(v) & 0xFFFFFC00u) | (1023u - ig);
}
__device__ __forceinline__ float keyval(u32 k) { return unford(k & 0xFFFFFC00u); }
__device__ __forceinline__ int keyidx(u32 k) { return 1023 - (int)(k & 1023u); }

// sorted-descending top-4 insert (u32)
__device__ __forceinline__ void ins4(u32* t, u32 k) {
    if (k > t[0])      { t[3] = t[2]; t[2] = t[1]; t[1] = t[0]; t[0] = k; }
    else if (k > t[1]) { t[3] = t[2]; t[2] = t[1]; t[1] = k; }
    else if (k > t[2]) { t[3] = t[2]; t[2] = k; }
    else if (k > t[3]) { t[3] = k; }
}

__device__ __forceinline__ uint32_t smem_to_u32(const void* p) {
    uint32_t a;
    asm("{ .reg .u64 t; cvta.to.shared.u64 t, %1; cvt.u32.u64 %0, t; }"
        : "=r"(a) : "l"(p));
    return a;
}
#define LDSM_X4(r0, r1, r2, r3, a) \
    asm volatile("ldmatrix.sync.aligned.m8n8.x4.shared.b16 {%0,%1,%2,%3}, [%4];" \
                 : "=r"(r0), "=r"(r1), "=r"(r2), "=r"(r3) : "r"(a))
#define LDSM_X2(r0, r1, a) \
    asm volatile("ldmatrix.sync.aligned.m8n8.x2.shared.b16 {%0,%1}, [%2];" \
                 : "=r"(r0), "=r"(r1) : "r"(a))
#define MMA_FP16(c, a, b) \
    asm volatile("mma.sync.aligned.m16n8k16.row.col.f32.f16.f16.f32 " \
                 "{%0,%1,%2,%3}, {%4,%5,%6,%7}, {%8,%9}, {%0,%1,%2,%3};" \
                 : "+f"((c)[0]), "+f"((c)[1]), "+f"((c)[2]), "+f"((c)[3]) \
                 : "r"((a)[0]), "r"((a)[1]), "r"((a)[2]), "r"((a)[3]), \
                   "r"((b)[0]), "r"((b)[1]))
#define CP16(dst, src) \
    asm volatile("cp.async.cg.shared.global [%0], [%1], 16;" \
                 :: "r"(dst), "l"(src))
#define CP_COMMIT() asm volatile("cp.async.commit_group;")
#define CP_WAIT0()  asm volatile("cp.async.wait_group 0;" ::: "memory")

// ---------------------------------------------------------------------------
// mega_kernel: all independent preprocessing + output_g as block ranges.
__global__ __launch_bounds__(256) void mega_kernel(
    const float* __restrict__ dq, const float* __restrict__ dk,
    const float* __restrict__ queue_d, const float* __restrict__ featk,
    const float* __restrict__ featq,
    const float* __restrict__ gq, const float* __restrict__ gk,
    const float* __restrict__ queue_g, float* __restrict__ out) {
    __shared__ float buf[4416];
    const int bx = blockIdx.x;
    const int tid = threadIdx.x;

    if (bx < 512) {
        // ---- normt ----
        const int which = bx >> 8;
        const int rr = bx & 255;
        const int b = rr >> 5;
        const int s0 = (rr & 31) * 32;
        const float* src = which ? dk : dq;
        float* dst = which ? g_dkt : g_dqt;
        float (*sm)[129] = reinterpret_cast<float (*)[129]>(buf);
        float (*red)[32] = reinterpret_cast<float (*)[32]>(buf + 4128);
        float* sinv = buf + 4384;
#pragma unroll
        for (int k = 0; k < 16; k++) {
            int idx = tid + k * 256;
            int d = idx >> 5, sl = idx & 31;
            sm[sl][d] = src[((size_t)b * D_ + d) * S_ + s0 + sl];
        }
        __syncthreads();
        {
            int sl = tid & 31, pp = tid >> 5;
            float ss = 0.0f;
#pragma unroll
            for (int d = pp * 16; d < pp * 16 + 16; d++) ss += sm[sl][d] * sm[sl][d];
            red[pp][sl] = ss;
        }
        __syncthreads();
        if (tid < 32) {
            float tot = 0.0f;
#pragma unroll
            for (int p = 0; p < 8; p++) tot += red[p][tid];
            sinv[tid] = rsqrtf(fmaxf(tot, 1e-24f));
        }
        __syncthreads();
#pragma unroll
        for (int k = 0; k < 16; k++) {
            int idx = tid + k * 256;
            int sl = idx >> 7, d = idx & 127;
            dst[((size_t)b * S_ + s0 + sl) * D_ + d] = sm[sl][d] * sinv[sl];
        }
    } else if (bx < 1024) {
        // ---- qconv ----
        const int q0 = (bx - 512) * 32;
        float (*sm)[129] = reinterpret_cast<float (*)[129]>(buf);
#pragma unroll
        for (int k = 0; k < 16; k++) {
            int idx = tid + k * 256;
            int d = idx >> 5, ql = idx & 31;
            sm[ql][d] = queue_d[(size_t)d * K_ + q0 + ql];
        }
        __syncthreads();
        uint2* qt2 = (uint2*)g_qt4;
        const int qt = q0 >> 7;
#pragma unroll
        for (int k = 0; k < 4; k++) {
            int idx = tid + k * 256;
            int ql = idx >> 5, dg = idx & 31;
            __half h[4];
#pragma unroll
            for (int e = 0; e < 4; e++) h[e] = __float2half(sm[ql][dg * 4 + e]);
            int row = (q0 + ql) & 127;
            uint2 packed;
            memcpy(&packed, h, 8);
            qt2[((size_t)(qt * 128 + row)) * 32 + dg] = packed;
        }
    } else if (bx < 1152) {
        // ---- fknorm ----
        const int r = bx - 1024;
        const int b = r >> 4;
        const int s = (r & 15) * 64 + (tid & 63);
        const int g = tid >> 6;
        float (*red)[64] = reinterpret_cast<float (*)[64]>(buf);
        const float* p = featk + (size_t)b * C_ * S_ + s;
        float ss = 0.0f;
#pragma unroll 8
        for (int c = g * 128; c < g * 128 + 128; c++) {
            float v = p[(size_t)c * S_];
            ss += v * v;
        }
        red[g][tid & 63] = ss;
        __syncthreads();
        if (g == 0) {
            float tot = red[0][tid] + red[1][tid] + red[2][tid] + red[3][tid];
            g_fkinv[b * S_ + s] = rsqrtf(fmaxf(tot, 1e-24f));
        }
    } else if (bx < 9344) {
        // ---- fsplit: transpose [b][c][s] -> [b][s][c], fp16 ----
        const int r = bx - 1152;
        const int z = r / 512;
        const int rem = r & 511;
        const int s0 = (rem & 31) * 32;
        const int c0 = (rem >> 5) * 32;
        const bool isk = z < 8;
        const int b = isk ? z : z - 8;
        const float* src = isk ? featk : featq;
        __half* dh = isk ? g_fkh : g_fqh;
        float (*tile)[33] = reinterpret_cast<float (*)[33]>(buf);
        const int tx = tid & 31, ty = tid >> 5;
#pragma unroll
        for (int rr = 0; rr < 4; rr++) {
            int c = c0 + ty * 4 + rr;
            tile[ty * 4 + rr][tx] = src[((size_t)b * C_ + c) * S_ + s0 + tx];
        }
        __syncthreads();
#pragma unroll
        for (int rr = 0; rr < 4; rr++) {
            int s = s0 + ty * 4 + rr;
            dh[((size_t)b * S_ + s) * C_ + c0 + tx] =
                __float2half(tile[tx][ty * 4 + rr]);
        }
    } else {
        // ---- outg ----
        const int r = bx - 9344;
        const int b = r >> 6;
        const int k = (r & 63) * 256 + tid;
        float v = 0.0f;
        if (tid < 128) v = gq[b * D_ + tid];
        buf[tid] = v * v;
        if (tid >= 128) buf[tid] = 0.0f;
        __syncthreads();
        for (int off = 128; off; off >>= 1) {
            if (tid < off) buf[tid] += buf[tid + off];
            __syncthreads();
        }
        float qsc = rsqrtf(fmaxf(buf[0], 1e-24f));
        __syncthreads();
        if (tid < 128) buf[256 + tid] = v * qsc;
        __syncthreads();
        float acc = 0.0f;
#pragma unroll 16
        for (int d = 0; d < D_; d++) acc += buf[256 + d] * queue_g[(size_t)d * K_ + k];
        out[OG + (size_t)b * (K_ + 1) + 1 + k] = acc * INV_TAU;
        if ((r & 63) == 0) {
            float w = 0.0f;
            if (tid < 128) w = gk[b * D_ + tid];
            buf[tid] = w * w;
            if (tid >= 128) buf[tid] = 0.0f;
            __syncthreads();
            for (int off = 128; off; off >>= 1) {
                if (tid < off) buf[tid] += buf[tid + off];
                __syncthreads();
            }
            float ksc = rsqrtf(fmaxf(buf[0], 1e-24f));
            __syncthreads();
            buf[tid] = (tid < 128) ? buf[256 + tid] * w * ksc : 0.0f;
            __syncthreads();
            for (int off = 128; off; off >>= 1) {
                if (tid < off) buf[tid] += buf[tid + off];
                __syncthreads();
            }
            if (tid == 0) {
                out[OG + (size_t)b * (K_ + 1)] = buf[0] * INV_TAU;
                out[TG + b] = 0.0f;
            }
        }
    }
}

// ---------------------------------------------------------------------------
// cosine: CTA = 128i x 32j (finer grid for wave packing), 8 warps
// (2 wm x 4 wn), warp tile 64x8. Single-pass fp16 mma on raw features.
constexpr int XSTRIDE = 80;
constexpr int STG_A_SZ = 128 * XSTRIDE;     // 10240
constexpr int STG_B_SZ = 32 * XSTRIDE;      // 2560
constexpr int STG_BYTES = STG_A_SZ + STG_B_SZ;  // 12800
constexpr int SMEM_COS = 2 * STG_BYTES;     // 25600

__global__ __launch_bounds__(256) void cos_mma_kernel() {
    extern __shared__ char smem[];
    __shared__ u32 smtop[2][4][8][4];
    __shared__ float sinv[128];
    const uint32_t sb = smem_to_u32(smem);
    const int tid = threadIdx.x;
    const int lane = tid & 31;
    const int wid = tid >> 5;
    const int wm = wid & 1;        // 64 i-rows
    const int wn = wid >> 1;       // 8 j-cols
    const int it = blockIdx.x, jt = blockIdx.y, b = blockIdx.z;
    const int i0 = it * 128, j0 = jt * 32;

    if (tid < 128) sinv[tid] = g_fkinv[b * S_ + i0 + tid];

    uint32_t aoff[4], boff;
    {
        int arow = wm * 64 + ((lane >> 3) & 1) * 8 + (lane & 7);
        int acol = ((lane >> 4) & 1) * 16;
#pragma unroll
        for (int i = 0; i < 4; i++) aoff[i] = (arow + i * 16) * XSTRIDE + acol;
        // ldmatrix.x2: lanes 0..15 supply addresses (2 8x8 matrices = k halves)
        int kh = (lane >> 3) & 1;
        int brow = lane & 7;
        boff = (wn * 8 + brow) * XSTRIDE + kh * 16;
    }

    auto load_stage = [&](int st, int kc) {
        uint32_t base = sb + st * STG_BYTES;
#pragma unroll
        for (int k = 0; k < 3; k++) {
            int idx = tid + k * 256;         // need 640 CP16s
            if (idx < 640) {
                bool isA = idx < 512;
                int rem = isA ? idx : idx - 512;
                int r = rem >> 2;
                int quad = rem & 3;
                int row = isA ? (i0 + r) : (j0 + r);
                const __half* s = (isA ? g_fkh : g_fqh) +
                                  ((size_t)(b * 1024 + row) * 512 + kc * 32 + quad * 8);
                uint32_t d = base + (isA ? 0 : STG_A_SZ) + r * XSTRIDE + quad * 16;
                CP16(d, s);
            }
        }
    };

    float acc[4][4];
#pragma unroll
    for (int i = 0; i < 4; i++)
#pragma unroll
        for (int r = 0; r < 4; r++) acc[i][r] = 0.0f;

    load_stage(0, 0);
    CP_COMMIT();
    CP_WAIT0();
    __syncthreads();

    for (int kc = 0; kc < 16; kc++) {
        const int st = kc & 1;
        if (kc < 15) { load_stage(st ^ 1, kc + 1); CP_COMMIT(); }
        const uint32_t base = sb + st * STG_BYTES;
#pragma unroll
        for (int kh = 0; kh < 2; kh++) {
            uint32_t Af[4][4], Bf[2];
#pragma unroll
            for (int i = 0; i < 4; i++)
                LDSM_X4(Af[i][0], Af[i][1], Af[i][2], Af[i][3],
                        base + aoff[i] + kh * 32);
            LDSM_X2(Bf[0], Bf[1], base + STG_A_SZ + boff + kh * 32);
#pragma unroll
            for (int i = 0; i < 4; i++)
                MMA_FP16(acc[i], Af[i], Bf);
        }
        if (kc < 15) CP_WAIT0();
        __syncthreads();
    }

    float sA[4], sB[4];
#pragma unroll
    for (int i = 0; i < 4; i++) {
        int rl = wm * 64 + i * 16 + (lane >> 2);
        sA[i] = sinv[rl];
        sB[i] = sinv[rl + 8];
    }

    // top-4 over this CTA's 128 i per column (8 cols per warp)
#pragma unroll
    for (int dj = 0; dj < 2; dj++) {
        u32 t[4] = {0, 0, 0, 0};
#pragma unroll
        for (int i = 0; i < 4; i++) {
            unsigned ig = (unsigned)(i0 + wm * 64 + i * 16 + (lane >> 2));
            ins4(t, mkkey(acc[i][dj] * sA[i], ig));
            ins4(t, mkkey(acc[i][dj + 2] * sB[i], ig + 8));
        }
#pragma unroll
        for (int m = 4; m <= 16; m <<= 1) {
            u32 o0 = __shfl_xor_sync(0xFFFFFFFFu, t[0], m);
            u32 o1 = __shfl_xor_sync(0xFFFFFFFFu, t[1], m);
            u32 o2 = __shfl_xor_sync(0xFFFFFFFFu, t[2], m);
            u32 o3 = __shfl_xor_sync(0xFFFFFFFFu, t[3], m);
            ins4(t, o0); ins4(t, o1); ins4(t, o2); ins4(t, o3);
        }
        if (lane < 4) {
            int j = 2 * lane + dj;
#pragma unroll
            for (int e = 0; e < 4; e++) smtop[wm][wn][j][e] = t[e];
        }
    }
    __syncthreads();
    if (tid < 32) {
        int wn2 = tid >> 3, j = tid & 7;
        u32 t[4];
#pragma unroll
        for (int e = 0; e < 4; e++) t[e] = smtop[0][wn2][j][e];
#pragma unroll
        for (int e = 0; e < 4; e++) ins4(t, smtop[1][wn2][j][e]);
        size_t col = (size_t)b * 1024 + j0 + wn2 * 8 + j;
#pragma unroll
        for (int e = 0; e < 4; e++) g_top4[col * 32 + it * 4 + e] = t[e];
    }
}

// ---------------------------------------------------------------------------
// fingather: warp per column. Exact argmax then gather matched row.
__global__ void fingather_kernel(const float* __restrict__ featq,
                                 const float* __restrict__ featk,
                                 float* __restrict__ out) {
    int col = blockIdx.x * 8 + (threadIdx.x >> 5);
    int lane = threadIdx.x & 31;
    int b = col >> 10, z = col & 1023;
    u32 key = g_top4[(size_t)col * 32 + lane];
    u32 m = key;
#pragma unroll
    for (int off = 16; off; off >>= 1)
        m = max(m, __shfl_xor_sync(0xFFFFFFFFu, m, off));
    float vmax = keyval(m);
    bool pass = keyval(key) >= vmax - MARGIN;
    unsigned mask = __ballot_sync(0xFFFFFFFFu, pass);
    u32 best = m;
    if (__popc(mask) > 1) {
        float bv = -1e30f;
        int bi = 0x7FFFFFFF;
        unsigned rem = mask;
        while (rem) {
            int c = __ffs(rem) - 1;
            rem &= rem - 1;
            int i = keyidx(__shfl_sync(0xFFFFFFFFu, key, c));
            const float* fkp = featk + (size_t)b * C_ * S_ + i;
            const float* fqp = featq + (size_t)b * C_ * S_ + z;
            float ex = 0.0f;
#pragma unroll 4
            for (int c0 = lane; c0 < C_; c0 += 32)
                ex += fkp[(size_t)c0 * S_] * fqp[(size_t)c0 * S_];
#pragma unroll
            for (int off = 16; off; off >>= 1)
                ex += __shfl_xor_sync(0xFFFFFFFFu, ex, off);
            ex *= g_fkinv[b * S_ + i];
            if (ex > bv || (ex == bv && i < bi)) { bv = ex; bi = i; }
        }
        best = mkkey(bv, (unsigned)bi);
    }
    int midx = keyidx(best);
    float4 x = ((const float4*)(g_dqt + ((size_t)b * S_ + midx) * D_))[lane];
    float4 y = ((const float4*)(g_dkt + ((size_t)b * S_ + z) * D_))[lane];
    float d = x.x * y.x + x.y * y.y + x.z * y.z + x.w * y.w;
#pragma unroll
    for (int off = 16; off; off >>= 1) d += __shfl_xor_sync(0xFFFFFFFFu, d, off);
    __half h[4] = {__float2half(x.x), __float2half(x.y),
                   __float2half(x.z), __float2half(x.w)};
    uint2 packed;
    memcpy(&packed, h, 8);
    ((uint2*)g_bt4)[((size_t)((b * 8 + (z >> 7)) * 128 + (z & 127))) * 32 + lane] =
        packed;
    if (lane == 0) out[OD + (size_t)b * (K_ + 1) * S_ + z] = d * INV_TAU;
    if (lane == 1) out[TD + b * S_ + z] = 0.0f;
}

// ---------------------------------------------------------------------------
// negd: CTA = 128q x 128z, 4 warps, warp tile 64x64; blockIdx.y selects a
// z-half (4 iters each) -> 2048 CTAs for fine wave packing.
constexpr int TSTRIDE = 272;
constexpr int TILE_SM = 128 * TSTRIDE;
constexpr int SM_A = 0;
constexpr int SM_B = TILE_SM;
constexpr int SMEM_NEGD = 3 * TILE_SM;             // 104448 -> 2 CTAs/SM

__device__ __forceinline__ void cp_tile128(uint32_t smDst, const uint4* src, int tid) {
#pragma unroll
    for (int k = 0; k < 16; k++) {
        int idx = tid + k * 128;
        int row = idx >> 4, w = idx & 15;
        CP16(smDst + row * TSTRIDE + w * 16, src + idx);
    }
}

__global__ __launch_bounds__(128, 2) void negd_mma_kernel(float* __restrict__ out) {
    extern __shared__ char smem[];
    const uint32_t sb = smem_to_u32(smem);
    const int tid = threadIdx.x;
    const int lane = tid & 31;
    const int wid = tid >> 5;
    const int wm = wid & 1;        // 64 q-rows
    const int wn = wid >> 1;       // 64 z-cols
    const int qt = blockIdx.x;
    const int zh = blockIdx.y;     // z-half: tiles [zh*4, zh*4+4)
    const int b = blockIdx.z;
    const int q0 = qt << 7;

    uint32_t aoff[4], b4off[4];
    {
        int arow = wm * 64 + ((lane >> 3) & 1) * 8 + (lane & 7);
        int acol = ((lane >> 4) & 1) * 16;
#pragma unroll
        for (int i = 0; i < 4; i++) aoff[i] = (arow + i * 16) * TSTRIDE + acol;
        int jsel = (lane >> 4) & 1;
        int kh = (lane >> 3) & 1;
        int brow = lane & 7;
#pragma unroll
        for (int jp = 0; jp < 4; jp++)
            b4off[jp] = (wn * 64 + (jp * 2 + jsel) * 8 + brow) * TSTRIDE + kh * 16;
    }

    cp_tile128(sb + SM_A, g_qt4 + (size_t)qt * 2048, tid);
    cp_tile128(sb + SM_B, g_bt4 + (size_t)(b * 8 + zh * 4) * 2048, tid);
    CP_COMMIT();
    CP_WAIT0();
    __syncthreads();

    for (int it = 0; it < 4; it++) {
        const int zt = zh * 4 + it;
        const int stage = it & 1;
        if (it < 3) {
            cp_tile128(sb + SM_B + (stage ^ 1) * TILE_SM,
                       g_bt4 + (size_t)(b * 8 + zt + 1) * 2048, tid);
            CP_COMMIT();
        }

        float acc[4][8][4];
#pragma unroll
        for (int i = 0; i < 4; i++)
#pragma unroll
            for (int j = 0; j < 8; j++)
#pragma unroll
                for (int r = 0; r < 4; r++) acc[i][j][r] = 0.0f;

        const uint32_t aB = sb + SM_A;
        const uint32_t bB = sb + SM_B + stage * TILE_SM;

#pragma unroll
        for (int ks = 0; ks < 8; ks++) {
            uint32_t Af[4][4], Bf[8][2];
#pragma unroll
            for (int i = 0; i < 4; i++)
                LDSM_X4(Af[i][0], Af[i][1], Af[i][2], Af[i][3], aB + aoff[i] + ks * 32);
#pragma unroll
            for (int jp = 0; jp < 4; jp++)
                LDSM_X4(Bf[jp * 2][0], Bf[jp * 2][1], Bf[jp * 2 + 1][0], Bf[jp * 2 + 1][1],
                        bB + b4off[jp] + ks * 32);
#pragma unroll
            for (int i = 0; i < 4; i++)
#pragma unroll
                for (int j = 0; j < 8; j++)
                    MMA_FP16(acc[i][j], Af[i], Bf[j]);
        }

#pragma unroll
        for (int i = 0; i < 4; i++) {
            int q = q0 + wm * 64 + i * 16 + (lane >> 2);
            float* rowp = out + OD + (size_t)(b * (K_ + 1) + 1 + q) * S_;
#pragma unroll
            for (int j = 0; j < 8; j++) {
                int z = zt * 128 + wn * 64 + j * 8 + 2 * (lane & 3);
                float2 w0 = {acc[i][j][0] * INV_TAU, acc[i][j][1] * INV_TAU};
                float2 w1 = {acc[i][j][2] * INV_TAU, acc[i][j][3] * INV_TAU};
                *reinterpret_cast<float2*>(rowp + z) = w0;
                *reinterpret_cast<float2*>(rowp + 8 * S_ + z) = w1;
            }
        }

        if (it < 3) CP_WAIT0();
        __syncthreads();
    }
}

// ---------------------------------------------------------------------------
extern "C" void kernel_launch(void* const* d_in, const int* in_sizes, int n_in,
                              void* d_out, int out_size) {
    const float* g_q     = (const float*)d_in[0];
    const float* g_k     = (const float*)d_in[1];
    const float* d_q     = (const float*)d_in[2];
    const float* d_k     = (const float*)d_in[3];
    const float* feat_q  = (const float*)d_in[4];
    const float* feat_k  = (const float*)d_in[5];
    const float* queue_g = (const float*)d_in[6];
    const float* queue_d = (const float*)d_in[7];
    float* out = (float*)d_out;

    cudaFuncSetAttribute(negd_mma_kernel,
                         cudaFuncAttributeMaxDynamicSharedMemorySize, SMEM_NEGD);
    cudaFuncSetAttribute(cos_mma_kernel,
                         cudaFuncAttributeMaxDynamicSharedMemorySize, SMEM_COS);

    mega_kernel<<<9856, 256>>>(d_q, d_k, queue_d, feat_k, feat_q,
                               g_q, g_k, queue_g, out);                 // 0
    cos_mma_kernel<<<dim3(8, 32, B_), 256, SMEM_COS>>>();               // 1
    fingather_kernel<<<1024, 256>>>(feat_q, feat_k, out);               // 2
    negd_mma_kernel<<<dim3(128, 2, B_), 128, SMEM_NEGD>>>(out);         // 3
}

// round 15
// speedup vs baseline: 1.0634x; 1.0634x over previous
#include <cuda_runtime.h>
#include <cuda_fp16.h>
#include <cstdint>

typedef unsigned long long u64;
typedef unsigned u32;

// Problem constants
constexpr int B_ = 8;
constexpr int D_ = 128;
constexpr int S_ = 1024;
constexpr int C_ = 512;
constexpr int K_ = 16384;
constexpr float INV_TAU = 5.0f;
constexpr float MARGIN = 3e-3f;

// Output layout (flattened concatenation, float32)
constexpr size_t OG = 0;
constexpr size_t TG = (size_t)B_ * (K_ + 1);
constexpr size_t OD = TG + B_;
constexpr size_t TD = OD + (size_t)B_ * (K_ + 1) * S_;

// Scratch (device globals; no allocation allowed)
__device__ float g_dqt[B_ * S_ * D_];   // normalized d_q, transposed [b][s][d]
__device__ float g_dkt[B_ * S_ * D_];   // normalized d_k, transposed [b][s][d]
__device__ float g_fkinv[B_ * S_];      // 1/||feat_k[:,i]||
__device__ u32   g_top4[B_ * S_ * 32];  // per (col, itile): top-4 packed keys

// fp16 transposed raw features: [b][s][c]
__device__ __half g_fkh[B_ * S_ * C_];
__device__ __half g_fqh[B_ * S_ * C_];

// fp16 row-major tiles for negd: [tile][row(128)][d(128)]
__device__ uint4 g_qt4[128 * 2048];     // queue_d
__device__ uint4 g_bt4[64 * 2048];      // gathered d_q (8b x 8 z-tiles of 128)

// ---------- helpers ----------
__device__ __forceinline__ unsigned ford(float f) {
    unsigned u = __float_as_uint(f);
    return (u & 0x80000000u) ? ~u : (u | 0x80000000u);
}
__device__ __forceinline__ float unford(unsigned x) {
    unsigned u = (x & 0x80000000u) ? (x & 0x7FFFFFFFu) : ~x;
    return __uint_as_float(u);
}

// packed key: [22b truncated ford(value)][10b (1023 - index)]
__device__ __forceinline__ u32 mkkey(float v, unsigned ig) {
    return (ford(v) & 0xFFFFFC00u) | (1023u - ig);
}
__device__ __forceinline__ float keyval(u32 k) { return unford(k & 0xFFFFFC00u); }
__device__ __forceinline__ int keyidx(u32 k) { return 1023 - (int)(k & 1023u); }

// sorted-descending top-4 insert (u32)
__device__ __forceinline__ void ins4(u32* t, u32 k) {
    if (k > t[0])      { t[3] = t[2]; t[2] = t[1]; t[1] = t[0]; t[0] = k; }
    else if (k > t[1]) { t[3] = t[2]; t[2] = t[1]; t[1] = k; }
    else if (k > t[2]) { t[3] = t[2]; t[2] = k; }
    else if (k > t[3]) { t[3] = k; }
}

__device__ __forceinline__ uint32_t smem_to_u32(const void* p) {
    uint32_t a;
    asm("{ .reg .u64 t; cvta.to.shared.u64 t, %1; cvt.u32.u64 %0, t; }"
        : "=r"(a) : "l"(p));
    return a;
}
#define LDSM_X4(r0, r1, r2, r3, a) \
    asm volatile("ldmatrix.sync.aligned.m8n8.x4.shared.b16 {%0,%1,%2,%3}, [%4];" \
                 : "=r"(r0), "=r"(r1), "=r"(r2), "=r"(r3) : "r"(a))
#define MMA_FP16(c, a, b) \
    asm volatile("mma.sync.aligned.m16n8k16.row.col.f32.f16.f16.f32 " \
                 "{%0,%1,%2,%3}, {%4,%5,%6,%7}, {%8,%9}, {%0,%1,%2,%3};" \
                 : "+f"((c)[0]), "+f"((c)[1]), "+f"((c)[2]), "+f"((c)[3]) \
                 : "r"((a)[0]), "r"((a)[1]), "r"((a)[2]), "r"((a)[3]), \
                   "r"((b)[0]), "r"((b)[1]))
#define CP16(dst, src) \
    asm volatile("cp.async.cg.shared.global [%0], [%1], 16;" \
                 :: "r"(dst), "l"(src))
#define CP_COMMIT() asm volatile("cp.async.commit_group;")
#define CP_WAIT0()  asm volatile("cp.async.wait_group 0;" ::: "memory")

// ---------------------------------------------------------------------------
// prep1: fsplit (feat transpose->fp16) + fknorm. 8320 blocks, 256 thr.
__global__ __launch_bounds__(256) void prep1_kernel(
    const float* __restrict__ featk, const float* __restrict__ featq) {
    __shared__ float buf[1184];
    const int bx = blockIdx.x;
    const int tid = threadIdx.x;

    if (bx < 8192) {
        // ---- fsplit ----
        const int z = bx / 512;
        const int rem = bx & 511;
        const int s0 = (rem & 31) * 32;
        const int c0 = (rem >> 5) * 32;
        const bool isk = z < 8;
        const int b = isk ? z : z - 8;
        const float* src = isk ? featk : featq;
        __half* dh = isk ? g_fkh : g_fqh;
        float (*tile)[33] = reinterpret_cast<float (*)[33]>(buf);
        const int tx = tid & 31, ty = tid >> 5;
#pragma unroll
        for (int rr = 0; rr < 4; rr++) {
            int c = c0 + ty * 4 + rr;
            tile[ty * 4 + rr][tx] = src[((size_t)b * C_ + c) * S_ + s0 + tx];
        }
        __syncthreads();
#pragma unroll
        for (int rr = 0; rr < 4; rr++) {
            int s = s0 + ty * 4 + rr;
            dh[((size_t)b * S_ + s) * C_ + c0 + tx] =
                __float2half(tile[tx][ty * 4 + rr]);
        }
    } else {
        // ---- fknorm ----
        const int r = bx - 8192;
        const int b = r >> 4;
        const int s = (r & 15) * 64 + (tid & 63);
        const int g = tid >> 6;
        float (*red)[64] = reinterpret_cast<float (*)[64]>(buf);
        const float* p = featk + (size_t)b * C_ * S_ + s;
        float ss = 0.0f;
#pragma unroll 8
        for (int c = g * 128; c < g * 128 + 128; c++) {
            float v = p[(size_t)c * S_];
            ss += v * v;
        }
        red[g][tid & 63] = ss;
        __syncthreads();
        if (g == 0) {
            float tot = red[0][tid] + red[1][tid] + red[2][tid] + red[3][tid];
            g_fkinv[b * S_ + s] = rsqrtf(fmaxf(tot, 1e-24f));
        }
    }
}

// ---------------------------------------------------------------------------
// cos_het: heterogeneous kernel.
//  [0, 1024)     cosine MMA tiles (128i x 64j, R11 config)
//  [1024, 1536)  normt: normalize d_q/d_k + transpose
//  [1536, 2048)  qconv: queue_d -> fp16 tiles
//  [2048, 2560)  outg: output_g
constexpr int XSTRIDE = 80;
constexpr int STG_A_SZ = 128 * XSTRIDE;     // 10240
constexpr int STG_B_SZ = 64 * XSTRIDE;      // 5120
constexpr int STG_BYTES = STG_A_SZ + STG_B_SZ;  // 15360
constexpr int SMEM_COS = 2 * STG_BYTES;     // 30720 dynamic (>= 17664 prep need)

__global__ __launch_bounds__(256, 3) void cos_het_kernel(
    const float* __restrict__ dq, const float* __restrict__ dk,
    const float* __restrict__ queue_d,
    const float* __restrict__ gq, const float* __restrict__ gk,
    const float* __restrict__ queue_g, float* __restrict__ out) {
    extern __shared__ char smem[];
    const int bxg = blockIdx.x;
    const int tid = threadIdx.x;

    if (bxg >= 1024) {
        float* buf = reinterpret_cast<float*>(smem);
        if (bxg < 1536) {
            // ---- normt ----
            const int r = bxg - 1024;
            const int which = r >> 8;
            const int rr = r & 255;
            const int b = rr >> 5;
            const int s0 = (rr & 31) * 32;
            const float* src = which ? dk : dq;
            float* dst = which ? g_dkt : g_dqt;
            float (*sm)[129] = reinterpret_cast<float (*)[129]>(buf);
            float (*red)[32] = reinterpret_cast<float (*)[32]>(buf + 4128);
            float* sinv = buf + 4384;
#pragma unroll
            for (int k = 0; k < 16; k++) {
                int idx = tid + k * 256;
                int d = idx >> 5, sl = idx & 31;
                sm[sl][d] = src[((size_t)b * D_ + d) * S_ + s0 + sl];
            }
            __syncthreads();
            {
                int sl = tid & 31, pp = tid >> 5;
                float ss = 0.0f;
#pragma unroll
                for (int d = pp * 16; d < pp * 16 + 16; d++) ss += sm[sl][d] * sm[sl][d];
                red[pp][sl] = ss;
            }
            __syncthreads();
            if (tid < 32) {
                float tot = 0.0f;
#pragma unroll
                for (int p = 0; p < 8; p++) tot += red[p][tid];
                sinv[tid] = rsqrtf(fmaxf(tot, 1e-24f));
            }
            __syncthreads();
#pragma unroll
            for (int k = 0; k < 16; k++) {
                int idx = tid + k * 256;
                int sl = idx >> 7, d = idx & 127;
                dst[((size_t)b * S_ + s0 + sl) * D_ + d] = sm[sl][d] * sinv[sl];
            }
        } else if (bxg < 2048) {
            // ---- qconv ----
            const int q0 = (bxg - 1536) * 32;
            float (*sm)[129] = reinterpret_cast<float (*)[129]>(buf);
#pragma unroll
            for (int k = 0; k < 16; k++) {
                int idx = tid + k * 256;
                int d = idx >> 5, ql = idx & 31;
                sm[ql][d] = queue_d[(size_t)d * K_ + q0 + ql];
            }
            __syncthreads();
            uint2* qt2 = (uint2*)g_qt4;
            const int qt = q0 >> 7;
#pragma unroll
            for (int k = 0; k < 4; k++) {
                int idx = tid + k * 256;
                int ql = idx >> 5, dg = idx & 31;
                __half h[4];
#pragma unroll
                for (int e = 0; e < 4; e++) h[e] = __float2half(sm[ql][dg * 4 + e]);
                int row = (q0 + ql) & 127;
                uint2 packed;
                memcpy(&packed, h, 8);
                qt2[((size_t)(qt * 128 + row)) * 32 + dg] = packed;
            }
        } else {
            // ---- outg ----
            const int r = bxg - 2048;
            const int b = r >> 6;
            const int k = (r & 63) * 256 + tid;
            float v = 0.0f;
            if (tid < 128) v = gq[b * D_ + tid];
            buf[tid] = v * v;
            if (tid >= 128) buf[tid] = 0.0f;
            __syncthreads();
            for (int off = 128; off; off >>= 1) {
                if (tid < off) buf[tid] += buf[tid + off];
                __syncthreads();
            }
            float qsc = rsqrtf(fmaxf(buf[0], 1e-24f));
            __syncthreads();
            if (tid < 128) buf[256 + tid] = v * qsc;
            __syncthreads();
            float acc = 0.0f;
#pragma unroll 16
            for (int d = 0; d < D_; d++)
                acc += buf[256 + d] * queue_g[(size_t)d * K_ + k];
            out[OG + (size_t)b * (K_ + 1) + 1 + k] = acc * INV_TAU;
            if ((r & 63) == 0) {
                float w = 0.0f;
                if (tid < 128) w = gk[b * D_ + tid];
                buf[tid] = w * w;
                if (tid >= 128) buf[tid] = 0.0f;
                __syncthreads();
                for (int off = 128; off; off >>= 1) {
                    if (tid < off) buf[tid] += buf[tid + off];
                    __syncthreads();
                }
                float ksc = rsqrtf(fmaxf(buf[0], 1e-24f));
                __syncthreads();
                buf[tid] = (tid < 128) ? buf[256 + tid] * w * ksc : 0.0f;
                __syncthreads();
                for (int off = 128; off; off >>= 1) {
                    if (tid < off) buf[tid] += buf[tid + off];
                    __syncthreads();
                }
                if (tid == 0) {
                    out[OG + (size_t)b * (K_ + 1)] = buf[0] * INV_TAU;
                    out[TG + b] = 0.0f;
                }
            }
        }
        return;
    }

    // ---- cosine tile (R11 config) ----
    __shared__ u32 smtop[2][4][16][4];
    __shared__ float sinvs[128];
    const uint32_t sb = smem_to_u32(smem);
    const int lane = tid & 31;
    const int wid = tid >> 5;
    const int wm = wid & 1;
    const int wn = wid >> 1;
    const int it = bxg & 7, jt = (bxg >> 3) & 15, b = bxg >> 7;
    const int i0 = it * 128, j0 = jt * 64;

    if (tid < 128) sinvs[tid] = g_fkinv[b * S_ + i0 + tid];

    uint32_t aoff[4], boff;
    {
        int arow = wm * 64 + ((lane >> 3) & 1) * 8 + (lane & 7);
        int acol = ((lane >> 4) & 1) * 16;
#pragma unroll
        for (int i = 0; i < 4; i++) aoff[i] = (arow + i * 16) * XSTRIDE + acol;
        int jsel = (lane >> 4) & 1;
        int kh = (lane >> 3) & 1;
        int brow = lane & 7;
        boff = (wn * 16 + jsel * 8 + brow) * XSTRIDE + kh * 16;
    }

    auto load_stage = [&](int st, int kc) {
        uint32_t base = sb + st * STG_BYTES;
#pragma unroll
        for (int k = 0; k < 3; k++) {
            int idx = tid + k * 256;
            bool isA = idx < 512;
            int rem = isA ? idx : idx - 512;
            int r = rem >> 2;
            int quad = rem & 3;
            int row = isA ? (i0 + r) : (j0 + r);
            const __half* s = (isA ? g_fkh : g_fqh) +
                              ((size_t)(b * 1024 + row) * 512 + kc * 32 + quad * 8);
            uint32_t d = base + (isA ? 0 : STG_A_SZ) + r * XSTRIDE + quad * 16;
            CP16(d, s);
        }
    };

    float acc[4][2][4];
#pragma unroll
    for (int i = 0; i < 4; i++)
#pragma unroll
        for (int j = 0; j < 2; j++)
#pragma unroll
            for (int r = 0; r < 4; r++) acc[i][j][r] = 0.0f;

    load_stage(0, 0);
    CP_COMMIT();
    CP_WAIT0();
    __syncthreads();

    for (int kc = 0; kc < 16; kc++) {
        const int st = kc & 1;
        if (kc < 15) { load_stage(st ^ 1, kc + 1); CP_COMMIT(); }
        const uint32_t base = sb + st * STG_BYTES;
#pragma unroll
        for (int kh = 0; kh < 2; kh++) {
            uint32_t Af[4][4], Bf[2][2];
#pragma unroll
            for (int i = 0; i < 4; i++)
                LDSM_X4(Af[i][0], Af[i][1], Af[i][2], Af[i][3],
                        base + aoff[i] + kh * 32);
            LDSM_X4(Bf[0][0], Bf[0][1], Bf[1][0], Bf[1][1],
                    base + STG_A_SZ + boff + kh * 32);
#pragma unroll
            for (int i = 0; i < 4; i++)
#pragma unroll
                for (int j = 0; j < 2; j++)
                    MMA_FP16(acc[i][j], Af[i], Bf[j]);
        }
        if (kc < 15) CP_WAIT0();
        __syncthreads();
    }

    float sA[4], sB[4];
#pragma unroll
    for (int i = 0; i < 4; i++) {
        int rl = wm * 64 + i * 16 + (lane >> 2);
        sA[i] = sinvs[rl];
        sB[i] = sinvs[rl + 8];
    }

#pragma unroll
    for (int jf = 0; jf < 2; jf++) {
#pragma unroll
        for (int dj = 0; dj < 2; dj++) {
            u32 t[4] = {0, 0, 0, 0};
#pragma unroll
            for (int i = 0; i < 4; i++) {
                unsigned ig = (unsigned)(i0 + wm * 64 + i * 16 + (lane >> 2));
                ins4(t, mkkey(acc[i][jf][dj] * sA[i], ig));
                ins4(t, mkkey(acc[i][jf][dj + 2] * sB[i], ig + 8));
            }
#pragma unroll
            for (int m = 4; m <= 16; m <<= 1) {
                u32 o0 = __shfl_xor_sync(0xFFFFFFFFu, t[0], m);
                u32 o1 = __shfl_xor_sync(0xFFFFFFFFu, t[1], m);
                u32 o2 = __shfl_xor_sync(0xFFFFFFFFu, t[2], m);
                u32 o3 = __shfl_xor_sync(0xFFFFFFFFu, t[3], m);
                ins4(t, o0); ins4(t, o1); ins4(t, o2); ins4(t, o3);
            }
            if (lane < 4) {
                int j = jf * 8 + 2 * lane + dj;
#pragma unroll
                for (int e = 0; e < 4; e++) smtop[wm][wn][j][e] = t[e];
            }
        }
    }
    __syncthreads();
    if (tid < 64) {
        int wn2 = tid >> 4, j = tid & 15;
        u32 t[4];
#pragma unroll
        for (int e = 0; e < 4; e++) t[e] = smtop[0][wn2][j][e];
#pragma unroll
        for (int e = 0; e < 4; e++) ins4(t, smtop[1][wn2][j][e]);
        size_t col = (size_t)b * 1024 + j0 + wn2 * 16 + j;
#pragma unroll
        for (int e = 0; e < 4; e++) g_top4[col * 32 + it * 4 + e] = t[e];
    }
}

// ---------------------------------------------------------------------------
// fingather: warp per column. Exact argmax then gather matched row.
__global__ void fingather_kernel(const float* __restrict__ featq,
                                 const float* __restrict__ featk,
                                 float* __restrict__ out) {
    int col = blockIdx.x * 8 + (threadIdx.x >> 5);
    int lane = threadIdx.x & 31;
    int b = col >> 10, z = col & 1023;
    u32 key = g_top4[(size_t)col * 32 + lane];
    u32 m = key;
#pragma unroll
    for (int off = 16; off; off >>= 1)
        m = max(m, __shfl_xor_sync(0xFFFFFFFFu, m, off));
    float vmax = keyval(m);
    bool pass = keyval(key) >= vmax - MARGIN;
    unsigned mask = __ballot_sync(0xFFFFFFFFu, pass);
    u32 best = m;
    if (__popc(mask) > 1) {
        float bv = -1e30f;
        int bi = 0x7FFFFFFF;
        unsigned rem = mask;
        while (rem) {
            int c = __ffs(rem) - 1;
            rem &= rem - 1;
            int i = keyidx(__shfl_sync(0xFFFFFFFFu, key, c));
            const float* fkp = featk + (size_t)b * C_ * S_ + i;
            const float* fqp = featq + (size_t)b * C_ * S_ + z;
            float ex = 0.0f;
#pragma unroll 4
            for (int c0 = lane; c0 < C_; c0 += 32)
                ex += fkp[(size_t)c0 * S_] * fqp[(size_t)c0 * S_];
#pragma unroll
            for (int off = 16; off; off >>= 1)
                ex += __shfl_xor_sync(0xFFFFFFFFu, ex, off);
            ex *= g_fkinv[b * S_ + i];
            if (ex > bv || (ex == bv && i < bi)) { bv = ex; bi = i; }
        }
        best = mkkey(bv, (unsigned)bi);
    }
    int midx = keyidx(best);
    float4 x = ((const float4*)(g_dqt + ((size_t)b * S_ + midx) * D_))[lane];
    float4 y = ((const float4*)(g_dkt + ((size_t)b * S_ + z) * D_))[lane];
    float d = x.x * y.x + x.y * y.y + x.z * y.z + x.w * y.w;
#pragma unroll
    for (int off = 16; off; off >>= 1) d += __shfl_xor_sync(0xFFFFFFFFu, d, off);
    __half h[4] = {__float2half(x.x), __float2half(x.y),
                   __float2half(x.z), __float2half(x.w)};
    uint2 packed;
    memcpy(&packed, h, 8);
    ((uint2*)g_bt4)[((size_t)((b * 8 + (z >> 7)) * 128 + (z & 127))) * 32 + lane] =
        packed;
    if (lane == 0) out[OD + (size_t)b * (K_ + 1) * S_ + z] = d * INV_TAU;
    if (lane == 1) out[TD + b * S_ + z] = 0.0f;
}

// ---------------------------------------------------------------------------
// negd: CTA = 128q x 128z, 4 warps, warp tile 64x64, 8 z-iters (R11 config).
constexpr int TSTRIDE = 272;
constexpr int TILE_SM = 128 * TSTRIDE;
constexpr int SM_A = 0;
constexpr int SM_B = TILE_SM;
constexpr int SMEM_NEGD = 3 * TILE_SM;             // 104448 -> 2 CTAs/SM

__device__ __forceinline__ void cp_tile128(uint32_t smDst, const uint4* src, int tid) {
#pragma unroll
    for (int k = 0; k < 16; k++) {
        int idx = tid + k * 128;
        int row = idx >> 4, w = idx & 15;
        CP16(smDst + row * TSTRIDE + w * 16, src + idx);
    }
}

__global__ __launch_bounds__(128, 2) void negd_mma_kernel(float* __restrict__ out) {
    extern __shared__ char smem[];
    const uint32_t sb = smem_to_u32(smem);
    const int tid = threadIdx.x;
    const int lane = tid & 31;
    const int wid = tid >> 5;
    const int wm = wid & 1;        // 64 q-rows
    const int wn = wid >> 1;       // 64 z-cols
    const int qt = blockIdx.x;
    const int b = blockIdx.y;
    const int q0 = qt << 7;

    uint32_t aoff[4], b4off[4];
    {
        int arow = wm * 64 + ((lane >> 3) & 1) * 8 + (lane & 7);
        int acol = ((lane >> 4) & 1) * 16;
#pragma unroll
        for (int i = 0; i < 4; i++) aoff[i] = (arow + i * 16) * TSTRIDE + acol;
        int jsel = (lane >> 4) & 1;
        int kh = (lane >> 3) & 1;
        int brow = lane & 7;
#pragma unroll
        for (int jp = 0; jp < 4; jp++)
            b4off[jp] = (wn * 64 + (jp * 2 + jsel) * 8 + brow) * TSTRIDE + kh * 16;
    }

    cp_tile128(sb + SM_A, g_qt4 + (size_t)qt * 2048, tid);
    cp_tile128(sb + SM_B, g_bt4 + (size_t)(b * 8) * 2048, tid);
    CP_COMMIT();
    CP_WAIT0();
    __syncthreads();

    for (int zt = 0; zt < 8; zt++) {
        const int stage = zt & 1;
        if (zt < 7) {
            cp_tile128(sb + SM_B + (stage ^ 1) * TILE_SM,
                       g_bt4 + (size_t)(b * 8 + zt + 1) * 2048, tid);
            CP_COMMIT();
        }

        float acc[4][8][4];
#pragma unroll
        for (int i = 0; i < 4; i++)
#pragma unroll
            for (int j = 0; j < 8; j++)
#pragma unroll
                for (int r = 0; r < 4; r++) acc[i][j][r] = 0.0f;

        const uint32_t aB = sb + SM_A;
        const uint32_t bB = sb + SM_B + stage * TILE_SM;

#pragma unroll
        for (int ks = 0; ks < 8; ks++) {
            uint32_t Af[4][4], Bf[8][2];
#pragma unroll
            for (int i = 0; i < 4; i++)
                LDSM_X4(Af[i][0], Af[i][1], Af[i][2], Af[i][3], aB + aoff[i] + ks * 32);
#pragma unroll
            for (int jp = 0; jp < 4; jp++)
                LDSM_X4(Bf[jp * 2][0], Bf[jp * 2][1], Bf[jp * 2 + 1][0], Bf[jp * 2 + 1][1],
                        bB + b4off[jp] + ks * 32);
#pragma unroll
            for (int i = 0; i < 4; i++)
#pragma unroll
                for (int j = 0; j < 8; j++)
                    MMA_FP16(acc[i][j], Af[i], Bf[j]);
        }

#pragma unroll
        for (int i = 0; i < 4; i++) {
            int q = q0 + wm * 64 + i * 16 + (lane >> 2);
            float* rowp = out + OD + (size_t)(b * (K_ + 1) + 1 + q) * S_;
#pragma unroll
            for (int j = 0; j < 8; j++) {
                int z = zt * 128 + wn * 64 + j * 8 + 2 * (lane & 3);
                float2 w0 = {acc[i][j][0] * INV_TAU, acc[i][j][1] * INV_TAU};
                float2 w1 = {acc[i][j][2] * INV_TAU, acc[i][j][3] * INV_TAU};
                *reinterpret_cast<float2*>(rowp + z) = w0;
                *reinterpret_cast<float2*>(rowp + 8 * S_ + z) = w1;
            }
        }

        if (zt < 7) CP_WAIT0();
        __syncthreads();
    }
}

// ---------------------------------------------------------------------------
extern "C" void kernel_launch(void* const* d_in, const int* in_sizes, int n_in,
                              void* d_out, int out_size) {
    const float* g_q     = (const float*)d_in[0];
    const float* g_k     = (const float*)d_in[1];
    const float* d_q     = (const float*)d_in[2];
    const float* d_k     = (const float*)d_in[3];
    const float* feat_q  = (const float*)d_in[4];
    const float* feat_k  = (const float*)d_in[5];
    const float* queue_g = (const float*)d_in[6];
    const float* queue_d = (const float*)d_in[7];
    float* out = (float*)d_out;

    cudaFuncSetAttribute(negd_mma_kernel,
                         cudaFuncAttributeMaxDynamicSharedMemorySize, SMEM_NEGD);
    cudaFuncSetAttribute(cos_het_kernel,
                         cudaFuncAttributeMaxDynamicSharedMemorySize, SMEM_COS);

    prep1_kernel<<<8320, 256>>>(feat_k, feat_q);                        // 0
    cos_het_kernel<<<2560, 256, SMEM_COS>>>(d_q, d_k, queue_d,
                                            g_q, g_k, queue_g, out);    // 1
    fingather_kernel<<<1024, 256>>>(feat_q, feat_k, out);               // 2
    negd_mma_kernel<<<dim3(128, B_), 128, SMEM_NEGD>>>(out);            // 3
}

// round 16
// speedup vs baseline: 1.1162x; 1.0497x over previous
#include <cuda_runtime.h>
#include <cuda_fp16.h>
#include <cstdint>

typedef unsigned long long u64;
typedef unsigned u32;

// Problem constants
constexpr int B_ = 8;
constexpr int D_ = 128;
constexpr int S_ = 1024;
constexpr int C_ = 512;
constexpr int K_ = 16384;
constexpr float INV_TAU = 5.0f;
constexpr float MARGIN = 3e-3f;

// Output layout (flattened concatenation, float32)
constexpr size_t OG = 0;
constexpr size_t TG = (size_t)B_ * (K_ + 1);
constexpr size_t OD = TG + B_;
constexpr size_t TD = OD + (size_t)B_ * (K_ + 1) * S_;

// Scratch (device globals; no allocation allowed)
__device__ float g_dqt[B_ * S_ * D_];   // normalized d_q, transposed [b][s][d]
__device__ float g_dkt[B_ * S_ * D_];   // normalized d_k, transposed [b][s][d]
__device__ float g_fkinv[B_ * S_];      // 1/||feat_k[:,i]||
__device__ u32   g_top2[B_ * S_ * 16];  // per (col, itile): top-2 packed keys

// fp16 transposed raw features: [b][s][c]
__device__ __half g_fkh[B_ * S_ * C_];
__device__ __half g_fqh[B_ * S_ * C_];

// fp16 row-major tiles for negd: [tile][row(128)][d(128)]
__device__ uint4 g_qt4[128 * 2048];     // queue_d
__device__ uint4 g_bt4[64 * 2048];      // gathered d_q (8b x 8 z-tiles of 128)

// ---------- helpers ----------
__device__ __forceinline__ unsigned ford(float f) {
    unsigned u = __float_as_uint(f);
    return (u & 0x80000000u) ? ~u : (u | 0x80000000u);
}
__device__ __forceinline__ float unford(unsigned x) {
    unsigned u = (x & 0x80000000u) ? (x & 0x7FFFFFFFu) : ~x;
    return __uint_as_float(u);
}

// packed key: [22b truncated ford(value)][10b (1023 - index)]
__device__ __forceinline__ u32 mkkey(float v, unsigned ig) {
    return (ford(v) & 0xFFFFFC00u) | (1023u - ig);
}
__device__ __forceinline__ float keyval(u32 k) { return unford(k & 0xFFFFFC00u); }
__device__ __forceinline__ int keyidx(u32 k) { return 1023 - (int)(k & 1023u); }

// top-2 insert (sorted descending)
__device__ __forceinline__ void ins2(u32& t0, u32& t1, u32 k) {
    if (k > t0) { t1 = t0; t0 = k; }
    else if (k > t1) { t1 = k; }
}

__device__ __forceinline__ uint32_t smem_to_u32(const void* p) {
    uint32_t a;
    asm("{ .reg .u64 t; cvta.to.shared.u64 t, %1; cvt.u32.u64 %0, t; }"
        : "=r"(a) : "l"(p));
    return a;
}
#define LDSM_X4(r0, r1, r2, r3, a) \
    asm volatile("ldmatrix.sync.aligned.m8n8.x4.shared.b16 {%0,%1,%2,%3}, [%4];" \
                 : "=r"(r0), "=r"(r1), "=r"(r2), "=r"(r3) : "r"(a))
#define MMA_FP16(c, a, b) \
    asm volatile("mma.sync.aligned.m16n8k16.row.col.f32.f16.f16.f32 " \
                 "{%0,%1,%2,%3}, {%4,%5,%6,%7}, {%8,%9}, {%0,%1,%2,%3};" \
                 : "+f"((c)[0]), "+f"((c)[1]), "+f"((c)[2]), "+f"((c)[3]) \
                 : "r"((a)[0]), "r"((a)[1]), "r"((a)[2]), "r"((a)[3]), \
                   "r"((b)[0]), "r"((b)[1]))
#define CP16(dst, src) \
    asm volatile("cp.async.cg.shared.global [%0], [%1], 16;" \
                 :: "r"(dst), "l"(src))
#define CP_COMMIT() asm volatile("cp.async.commit_group;")
#define CP_WAIT0()  asm volatile("cp.async.wait_group 0;" ::: "memory")

// ---------------------------------------------------------------------------
// mega_kernel: all independent preprocessing + output_g as block ranges.
__global__ __launch_bounds__(256) void mega_kernel(
    const float* __restrict__ dq, const float* __restrict__ dk,
    const float* __restrict__ queue_d, const float* __restrict__ featk,
    const float* __restrict__ featq,
    const float* __restrict__ gq, const float* __restrict__ gk,
    const float* __restrict__ queue_g, float* __restrict__ out) {
    __shared__ float buf[4416];
    const int bx = blockIdx.x;
    const int tid = threadIdx.x;

    if (bx < 512) {
        // ---- normt ----
        const int which = bx >> 8;
        const int rr = bx & 255;
        const int b = rr >> 5;
        const int s0 = (rr & 31) * 32;
        const float* src = which ? dk : dq;
        float* dst = which ? g_dkt : g_dqt;
        float (*sm)[129] = reinterpret_cast<float (*)[129]>(buf);
        float (*red)[32] = reinterpret_cast<float (*)[32]>(buf + 4128);
        float* sinv = buf + 4384;
#pragma unroll
        for (int k = 0; k < 16; k++) {
            int idx = tid + k * 256;
            int d = idx >> 5, sl = idx & 31;
            sm[sl][d] = src[((size_t)b * D_ + d) * S_ + s0 + sl];
        }
        __syncthreads();
        {
            int sl = tid & 31, pp = tid >> 5;
            float ss = 0.0f;
#pragma unroll
            for (int d = pp * 16; d < pp * 16 + 16; d++) ss += sm[sl][d] * sm[sl][d];
            red[pp][sl] = ss;
        }
        __syncthreads();
        if (tid < 32) {
            float tot = 0.0f;
#pragma unroll
            for (int p = 0; p < 8; p++) tot += red[p][tid];
            sinv[tid] = rsqrtf(fmaxf(tot, 1e-24f));
        }
        __syncthreads();
#pragma unroll
        for (int k = 0; k < 16; k++) {
            int idx = tid + k * 256;
            int sl = idx >> 7, d = idx & 127;
            dst[((size_t)b * S_ + s0 + sl) * D_ + d] = sm[sl][d] * sinv[sl];
        }
    } else if (bx < 1024) {
        // ---- qconv ----
        const int q0 = (bx - 512) * 32;
        float (*sm)[129] = reinterpret_cast<float (*)[129]>(buf);
#pragma unroll
        for (int k = 0; k < 16; k++) {
            int idx = tid + k * 256;
            int d = idx >> 5, ql = idx & 31;
            sm[ql][d] = queue_d[(size_t)d * K_ + q0 + ql];
        }
        __syncthreads();
        uint2* qt2 = (uint2*)g_qt4;
        const int qt = q0 >> 7;
#pragma unroll
        for (int k = 0; k < 4; k++) {
            int idx = tid + k * 256;
            int ql = idx >> 5, dg = idx & 31;
            __half h[4];
#pragma unroll
            for (int e = 0; e < 4; e++) h[e] = __float2half(sm[ql][dg * 4 + e]);
            int row = (q0 + ql) & 127;
            uint2 packed;
            memcpy(&packed, h, 8);
            qt2[((size_t)(qt * 128 + row)) * 32 + dg] = packed;
        }
    } else if (bx < 1152) {
        // ---- fknorm ----
        const int r = bx - 1024;
        const int b = r >> 4;
        const int s = (r & 15) * 64 + (tid & 63);
        const int g = tid >> 6;
        float (*red)[64] = reinterpret_cast<float (*)[64]>(buf);
        const float* p = featk + (size_t)b * C_ * S_ + s;
        float ss = 0.0f;
#pragma unroll 8
        for (int c = g * 128; c < g * 128 + 128; c++) {
            float v = p[(size_t)c * S_];
            ss += v * v;
        }
        red[g][tid & 63] = ss;
        __syncthreads();
        if (g == 0) {
            float tot = red[0][tid] + red[1][tid] + red[2][tid] + red[3][tid];
            g_fkinv[b * S_ + s] = rsqrtf(fmaxf(tot, 1e-24f));
        }
    } else if (bx < 9344) {
        // ---- fsplit: transpose [b][c][s] -> [b][s][c], fp16 ----
        const int r = bx - 1152;
        const int z = r / 512;
        const int rem = r & 511;
        const int s0 = (rem & 31) * 32;
        const int c0 = (rem >> 5) * 32;
        const bool isk = z < 8;
        const int b = isk ? z : z - 8;
        const float* src = isk ? featk : featq;
        __half* dh = isk ? g_fkh : g_fqh;
        float (*tile)[33] = reinterpret_cast<float (*)[33]>(buf);
        const int tx = tid & 31, ty = tid >> 5;
#pragma unroll
        for (int rr = 0; rr < 4; rr++) {
            int c = c0 + ty * 4 + rr;
            tile[ty * 4 + rr][tx] = src[((size_t)b * C_ + c) * S_ + s0 + tx];
        }
        __syncthreads();
#pragma unroll
        for (int rr = 0; rr < 4; rr++) {
            int s = s0 + ty * 4 + rr;
            dh[((size_t)b * S_ + s) * C_ + c0 + tx] =
                __float2half(tile[tx][ty * 4 + rr]);
        }
    } else {
        // ---- outg ----
        const int r = bx - 9344;
        const int b = r >> 6;
        const int k = (r & 63) * 256 + tid;
        float v = 0.0f;
        if (tid < 128) v = gq[b * D_ + tid];
        buf[tid] = v * v;
        if (tid >= 128) buf[tid] = 0.0f;
        __syncthreads();
        for (int off = 128; off; off >>= 1) {
            if (tid < off) buf[tid] += buf[tid + off];
            __syncthreads();
        }
        float qsc = rsqrtf(fmaxf(buf[0], 1e-24f));
        __syncthreads();
        if (tid < 128) buf[256 + tid] = v * qsc;
        __syncthreads();
        float acc = 0.0f;
#pragma unroll 16
        for (int d = 0; d < D_; d++) acc += buf[256 + d] * queue_g[(size_t)d * K_ + k];
        out[OG + (size_t)b * (K_ + 1) + 1 + k] = acc * INV_TAU;
        if ((r & 63) == 0) {
            float w = 0.0f;
            if (tid < 128) w = gk[b * D_ + tid];
            buf[tid] = w * w;
            if (tid >= 128) buf[tid] = 0.0f;
            __syncthreads();
            for (int off = 128; off; off >>= 1) {
                if (tid < off) buf[tid] += buf[tid + off];
                __syncthreads();
            }
            float ksc = rsqrtf(fmaxf(buf[0], 1e-24f));
            __syncthreads();
            buf[tid] = (tid < 128) ? buf[256 + tid] * w * ksc : 0.0f;
            __syncthreads();
            for (int off = 128; off; off >>= 1) {
                if (tid < off) buf[tid] += buf[tid + off];
                __syncthreads();
            }
            if (tid == 0) {
                out[OG + (size_t)b * (K_ + 1)] = buf[0] * INV_TAU;
                out[TG + b] = 0.0f;
            }
        }
    }
}

// ---------------------------------------------------------------------------
// cosine: CTA = 128i x 64j, 8 warps (2 wm x 4 wn), warp tile 64x16.
// Streaming-pointer stage loads + top-2 epilogue (lean ALU path).
constexpr int XSTRIDE = 80;
constexpr int STG_A_SZ = 128 * XSTRIDE;     // 10240
constexpr int STG_B_SZ = 64 * XSTRIDE;      // 5120
constexpr int STG_BYTES = STG_A_SZ + STG_B_SZ;  // 15360
constexpr int SMEM_COS = 2 * STG_BYTES;     // 30720

__global__ __launch_bounds__(256, 3) void cos_mma_kernel() {
    extern __shared__ char smem[];
    __shared__ u32 smtop[2][4][16][2];
    __shared__ float sinv[128];
    const uint32_t sb = smem_to_u32(smem);
    const int tid = threadIdx.x;
    const int lane = tid & 31;
    const int wid = tid >> 5;
    const int wm = wid & 1;
    const int wn = wid >> 1;
    const int it = blockIdx.x, jt = blockIdx.y, b = blockIdx.z;
    const int i0 = it * 128, j0 = jt * 64;

    if (tid < 128) sinv[tid] = g_fkinv[b * S_ + i0 + tid];

    uint32_t aoff[4], boff;
    {
        int arow = wm * 64 + ((lane >> 3) & 1) * 8 + (lane & 7);
        int acol = ((lane >> 4) & 1) * 16;
#pragma unroll
        for (int i = 0; i < 4; i++) aoff[i] = (arow + i * 16) * XSTRIDE + acol;
        int jsel = (lane >> 4) & 1;
        int kh = (lane >> 3) & 1;
        int brow = lane & 7;
        boff = (wn * 16 + jsel * 8 + brow) * XSTRIDE + kh * 16;
    }

    // streaming pointers: computed once, src advances 32 halfs per kc
    const __half* srcp[3];
    uint32_t dsto[3];
    {
#pragma unroll
        for (int k = 0; k < 3; k++) {
            int idx = tid + k * 256;
            bool isA = idx < 512;
            int rem = isA ? idx : idx - 512;
            int r = rem >> 2;
            int quad = rem & 3;
            int row = isA ? (i0 + r) : (j0 + r);
            srcp[k] = (isA ? g_fkh : g_fqh) +
                      ((size_t)(b * 1024 + row) * 512 + quad * 8);
            dsto[k] = (isA ? 0u : (u32)STG_A_SZ) + r * XSTRIDE + quad * 16;
        }
    }
    auto load_stage = [&](int st, int kc) {
        uint32_t base = sb + st * STG_BYTES;
        int koff = kc * 32;
#pragma unroll
        for (int k = 0; k < 3; k++) CP16(base + dsto[k], srcp[k] + koff);
    };

    float acc[4][2][4];
#pragma unroll
    for (int i = 0; i < 4; i++)
#pragma unroll
        for (int j = 0; j < 2; j++)
#pragma unroll
            for (int r = 0; r < 4; r++) acc[i][j][r] = 0.0f;

    load_stage(0, 0);
    CP_COMMIT();
    CP_WAIT0();
    __syncthreads();

    for (int kc = 0; kc < 16; kc++) {
        const int st = kc & 1;
        if (kc < 15) { load_stage(st ^ 1, kc + 1); CP_COMMIT(); }
        const uint32_t base = sb + st * STG_BYTES;
#pragma unroll
        for (int kh = 0; kh < 2; kh++) {
            uint32_t Af[4][4], Bf[2][2];
#pragma unroll
            for (int i = 0; i < 4; i++)
                LDSM_X4(Af[i][0], Af[i][1], Af[i][2], Af[i][3],
                        base + aoff[i] + kh * 32);
            LDSM_X4(Bf[0][0], Bf[0][1], Bf[1][0], Bf[1][1],
                    base + STG_A_SZ + boff + kh * 32);
#pragma unroll
            for (int i = 0; i < 4; i++)
#pragma unroll
                for (int j = 0; j < 2; j++)
                    MMA_FP16(acc[i][j], Af[i], Bf[j]);
        }
        if (kc < 15) CP_WAIT0();
        __syncthreads();
    }

    float sA[4], sB[4];
#pragma unroll
    for (int i = 0; i < 4; i++) {
        int rl = wm * 64 + i * 16 + (lane >> 2);
        sA[i] = sinv[rl];
        sB[i] = sinv[rl + 8];
    }

    // top-2 over this CTA's 128 i per column j (scaled values)
#pragma unroll
    for (int jf = 0; jf < 2; jf++) {
#pragma unroll
        for (int dj = 0; dj < 2; dj++) {
            u32 t0 = 0, t1 = 0;
#pragma unroll
            for (int i = 0; i < 4; i++) {
                unsigned ig = (unsigned)(i0 + wm * 64 + i * 16 + (lane >> 2));
                ins2(t0, t1, mkkey(acc[i][jf][dj] * sA[i], ig));
                ins2(t0, t1, mkkey(acc[i][jf][dj + 2] * sB[i], ig + 8));
            }
#pragma unroll
            for (int m = 4; m <= 16; m <<= 1) {
                u32 o0 = __shfl_xor_sync(0xFFFFFFFFu, t0, m);
                u32 o1 = __shfl_xor_sync(0xFFFFFFFFu, t1, m);
                ins2(t0, t1, o0);
                ins2(t0, t1, o1);
            }
            if (lane < 4) {
                int j = jf * 8 + 2 * lane + dj;
                smtop[wm][wn][j][0] = t0;
                smtop[wm][wn][j][1] = t1;
            }
        }
    }
    __syncthreads();
    if (tid < 64) {
        int wn2 = tid >> 4, j = tid & 15;
        u32 t0 = smtop[0][wn2][j][0], t1 = smtop[0][wn2][j][1];
        ins2(t0, t1, smtop[1][wn2][j][0]);
        ins2(t0, t1, smtop[1][wn2][j][1]);
        size_t col = (size_t)b * 1024 + j0 + wn2 * 16 + j;
        g_top2[col * 16 + it * 2] = t0;
        g_top2[col * 16 + it * 2 + 1] = t1;
    }
}

// ---------------------------------------------------------------------------
// fingather: warp per column. Exact argmax (lanes 0..15 hold keys) then
// gather matched row: pos_d, B-tile, output_d row0, target_d.
__global__ void fingather_kernel(const float* __restrict__ featq,
                                 const float* __restrict__ featk,
                                 float* __restrict__ out) {
    int col = blockIdx.x * 8 + (threadIdx.x >> 5);
    int lane = threadIdx.x & 31;
    int b = col >> 10, z = col & 1023;
    u32 key = (lane < 16) ? g_top2[(size_t)col * 16 + lane] : 0u;
    u32 m = key;
#pragma unroll
    for (int off = 16; off; off >>= 1)
        m = max(m, __shfl_xor_sync(0xFFFFFFFFu, m, off));
    float vmax = keyval(m);
    bool pass = keyval(key) >= vmax - MARGIN;
    unsigned mask = __ballot_sync(0xFFFFFFFFu, pass);
    u32 best = m;
    if (__popc(mask) > 1) {
        float bv = -1e30f;
        int bi = 0x7FFFFFFF;
        unsigned rem = mask;
        while (rem) {
            int c = __ffs(rem) - 1;
            rem &= rem - 1;
            int i = keyidx(__shfl_sync(0xFFFFFFFFu, key, c));
            const float* fkp = featk + (size_t)b * C_ * S_ + i;
            const float* fqp = featq + (size_t)b * C_ * S_ + z;
            float ex = 0.0f;
#pragma unroll 4
            for (int c0 = lane; c0 < C_; c0 += 32)
                ex += fkp[(size_t)c0 * S_] * fqp[(size_t)c0 * S_];
#pragma unroll
            for (int off = 16; off; off >>= 1)
                ex += __shfl_xor_sync(0xFFFFFFFFu, ex, off);
            ex *= g_fkinv[b * S_ + i];
            if (ex > bv || (ex == bv && i < bi)) { bv = ex; bi = i; }
        }
        best = mkkey(bv, (unsigned)bi);
    }
    int midx = keyidx(best);
    float4 x = ((const float4*)(g_dqt + ((size_t)b * S_ + midx) * D_))[lane];
    float4 y = ((const float4*)(g_dkt + ((size_t)b * S_ + z) * D_))[lane];
    float d = x.x * y.x + x.y * y.y + x.z * y.z + x.w * y.w;
#pragma unroll
    for (int off = 16; off; off >>= 1) d += __shfl_xor_sync(0xFFFFFFFFu, d, off);
    __half h[4] = {__float2half(x.x), __float2half(x.y),
                   __float2half(x.z), __float2half(x.w)};
    uint2 packed;
    memcpy(&packed, h, 8);
    ((uint2*)g_bt4)[((size_t)((b * 8 + (z >> 7)) * 128 + (z & 127))) * 32 + lane] =
        packed;
    if (lane == 0) out[OD + (size_t)b * (K_ + 1) * S_ + z] = d * INV_TAU;
    if (lane == 1) out[TD + b * S_ + z] = 0.0f;
}

// ---------------------------------------------------------------------------
// negd: CTA = 128q x 128z, 4 warps, warp tile 64x64, 8 z-iters (R11 config).
constexpr int TSTRIDE = 272;
constexpr int TILE_SM = 128 * TSTRIDE;
constexpr int SM_A = 0;
constexpr int SM_B = TILE_SM;
constexpr int SMEM_NEGD = 3 * TILE_SM;             // 104448 -> 2 CTAs/SM

__device__ __forceinline__ void cp_tile128(uint32_t smDst, const uint4* src, int tid) {
#pragma unroll
    for (int k = 0; k < 16; k++) {
        int idx = tid + k * 128;
        int row = idx >> 4, w = idx & 15;
        CP16(smDst + row * TSTRIDE + w * 16, src + idx);
    }
}

__global__ __launch_bounds__(128, 2) void negd_mma_kernel(float* __restrict__ out) {
    extern __shared__ char smem[];
    const uint32_t sb = smem_to_u32(smem);
    const int tid = threadIdx.x;
    const int lane = tid & 31;
    const int wid = tid >> 5;
    const int wm = wid & 1;        // 64 q-rows
    const int wn = wid >> 1;       // 64 z-cols
    const int qt = blockIdx.x;
    const int b = blockIdx.y;
    const int q0 = qt << 7;

    uint32_t aoff[4], b4off[4];
    {
        int arow = wm * 64 + ((lane >> 3) & 1) * 8 + (lane & 7);
        int acol = ((lane >> 4) & 1) * 16;
#pragma unroll
        for (int i = 0; i < 4; i++) aoff[i] = (arow + i * 16) * TSTRIDE + acol;
        int jsel = (lane >> 4) & 1;
        int kh = (lane >> 3) & 1;
        int brow = lane & 7;
#pragma unroll
        for (int jp = 0; jp < 4; jp++)
            b4off[jp] = (wn * 64 + (jp * 2 + jsel) * 8 + brow) * TSTRIDE + kh * 16;
    }

    cp_tile128(sb + SM_A, g_qt4 + (size_t)qt * 2048, tid);
    cp_tile128(sb + SM_B, g_bt4 + (size_t)(b * 8) * 2048, tid);
    CP_COMMIT();
    CP_WAIT0();
    __syncthreads();

    for (int zt = 0; zt < 8; zt++) {
        const int stage = zt & 1;
        if (zt < 7) {
            cp_tile128(sb + SM_B + (stage ^ 1) * TILE_SM,
                       g_bt4 + (size_t)(b * 8 + zt + 1) * 2048, tid);
            CP_COMMIT();
        }

        float acc[4][8][4];
#pragma unroll
        for (int i = 0; i < 4; i++)
#pragma unroll
            for (int j = 0; j < 8; j++)
#pragma unroll
                for (int r = 0; r < 4; r++) acc[i][j][r] = 0.0f;

        const uint32_t aB = sb + SM_A;
        const uint32_t bB = sb + SM_B + stage * TILE_SM;

#pragma unroll
        for (int ks = 0; ks < 8; ks++) {
            uint32_t Af[4][4], Bf[8][2];
#pragma unroll
            for (int i = 0; i < 4; i++)
                LDSM_X4(Af[i][0], Af[i][1], Af[i][2], Af[i][3], aB + aoff[i] + ks * 32);
#pragma unroll
            for (int jp = 0; jp < 4; jp++)
                LDSM_X4(Bf[jp * 2][0], Bf[jp * 2][1], Bf[jp * 2 + 1][0], Bf[jp * 2 + 1][1],
                        bB + b4off[jp] + ks * 32);
#pragma unroll
            for (int i = 0; i < 4; i++)
#pragma unroll
                for (int j = 0; j < 8; j++)
                    MMA_FP16(acc[i][j], Af[i], Bf[j]);
        }

#pragma unroll
        for (int i = 0; i < 4; i++) {
            int q = q0 + wm * 64 + i * 16 + (lane >> 2);
            float* rowp = out + OD + (size_t)(b * (K_ + 1) + 1 + q) * S_;
#pragma unroll
            for (int j = 0; j < 8; j++) {
                int z = zt * 128 + wn * 64 + j * 8 + 2 * (lane & 3);
                float2 w0 = {acc[i][j][0] * INV_TAU, acc[i][j][1] * INV_TAU};
                float2 w1 = {acc[i][j][2] * INV_TAU, acc[i][j][3] * INV_TAU};
                *reinterpret_cast<float2*>(rowp + z) = w0;
                *reinterpret_cast<float2*>(rowp + 8 * S_ + z) = w1;
            }
        }

        if (zt < 7) CP_WAIT0();
        __syncthreads();
    }
}

// ---------------------------------------------------------------------------
extern "C" void kernel_launch(void* const* d_in, const int* in_sizes, int n_in,
                              void* d_out, int out_size) {
    const float* g_q     = (const float*)d_in[0];
    const float* g_k     = (const float*)d_in[1];
    const float* d_q     = (const float*)d_in[2];
    const float* d_k     = (const float*)d_in[3];
    const float* feat_q  = (const float*)d_in[4];
    const float* feat_k  = (const float*)d_in[5];
    const float* queue_g = (const float*)d_in[6];
    const float* queue_d = (const float*)d_in[7];
    float* out = (float*)d_out;

    cudaFuncSetAttribute(negd_mma_kernel,
                         cudaFuncAttributeMaxDynamicSharedMemorySize, SMEM_NEGD);
    cudaFuncSetAttribute(cos_mma_kernel,
                         cudaFuncAttributeMaxDynamicSharedMemorySize, SMEM_COS);

    mega_kernel<<<9856, 256>>>(d_q, d_k, queue_d, feat_k, feat_q,
                               g_q, g_k, queue_g, out);                 // 0
    cos_mma_kernel<<<dim3(8, 16, B_), 256, SMEM_COS>>>();               // 1
    fingather_kernel<<<1024, 256>>>(feat_q, feat_k, out);               // 2
    negd_mma_kernel<<<dim3(128, B_), 128, SMEM_NEGD>>>(out);            // 3
}

// round 17
// speedup vs baseline: 1.1349x; 1.0168x over previous
#include <cuda_runtime.h>
#include <cuda_fp16.h>
#include <cstdint>

typedef unsigned long long u64;
typedef unsigned u32;

// Problem constants
constexpr int B_ = 8;
constexpr int D_ = 128;
constexpr int S_ = 1024;
constexpr int C_ = 512;
constexpr int K_ = 16384;
constexpr float INV_TAU = 5.0f;
constexpr float MARGIN = 3e-3f;

// Output layout (flattened concatenation, float32)
constexpr size_t OG = 0;
constexpr size_t TG = (size_t)B_ * (K_ + 1);
constexpr size_t OD = TG + B_;
constexpr size_t TD = OD + (size_t)B_ * (K_ + 1) * S_;

// Scratch (device globals; no allocation allowed)
__device__ float g_dqt[B_ * S_ * D_];   // normalized d_q, transposed [b][s][d]
__device__ float g_dkt[B_ * S_ * D_];   // normalized d_k, transposed [b][s][d]
__device__ float g_fkinv[B_ * S_];      // 1/||feat_k[:,i]||
__device__ u32   g_top2[B_ * S_ * 16];  // per (col, itile): top-2 packed keys

// fp16 transposed raw features: [b][s][c]
__device__ __half g_fkh[B_ * S_ * C_];
__device__ __half g_fqh[B_ * S_ * C_];

// fp16 row-major tiles for negd: [tile][row(128)][d(128)]
__device__ uint4 g_qt4[128 * 2048];     // queue_d
__device__ uint4 g_bt4[64 * 2048];      // gathered d_q (8b x 8 z-tiles of 128)

// ---------- helpers ----------
__device__ __forceinline__ unsigned ford(float f) {
    unsigned u = __float_as_uint(f);
    return (u & 0x80000000u) ? ~u : (u | 0x80000000u);
}
__device__ __forceinline__ float unford(unsigned x) {
    unsigned u = (x & 0x80000000u) ? (x & 0x7FFFFFFFu) : ~x;
    return __uint_as_float(u);
}

// packed key: [22b truncated ford(value)][10b (1023 - index)]
__device__ __forceinline__ u32 mkkey(float v, unsigned ig) {
    return (ford(v) & 0xFFFFFC00u) | (1023u - ig);
}
__device__ __forceinline__ float keyval(u32 k) { return unford(k & 0xFFFFFC00u); }
__device__ __forceinline__ int keyidx(u32 k) { return 1023 - (int)(k & 1023u); }

// top-2 insert (sorted descending)
__device__ __forceinline__ void ins2(u32& t0, u32& t1, u32 k) {
    if (k > t0) { t1 = t0; t0 = k; }
    else if (k > t1) { t1 = k; }
}

__device__ __forceinline__ uint32_t smem_to_u32(const void* p) {
    uint32_t a;
    asm("{ .reg .u64 t; cvta.to.shared.u64 t, %1; cvt.u32.u64 %0, t; }"
        : "=r"(a) : "l"(p));
    return a;
}
#define LDSM_X4(r0, r1, r2, r3, a) \
    asm volatile("ldmatrix.sync.aligned.m8n8.x4.shared.b16 {%0,%1,%2,%3}, [%4];" \
                 : "=r"(r0), "=r"(r1), "=r"(r2), "=r"(r3) : "r"(a))
#define MMA_FP16(c, a, b) \
    asm volatile("mma.sync.aligned.m16n8k16.row.col.f32.f16.f16.f32 " \
                 "{%0,%1,%2,%3}, {%4,%5,%6,%7}, {%8,%9}, {%0,%1,%2,%3};" \
                 : "+f"((c)[0]), "+f"((c)[1]), "+f"((c)[2]), "+f"((c)[3]) \
                 : "r"((a)[0]), "r"((a)[1]), "r"((a)[2]), "r"((a)[3]), \
                   "r"((b)[0]), "r"((b)[1]))
#define CP16(dst, src) \
    asm volatile("cp.async.cg.shared.global [%0], [%1], 16;" \
                 :: "r"(dst), "l"(src))
#define CP_COMMIT() asm volatile("cp.async.commit_group;")
#define CP_WAIT0()  asm volatile("cp.async.wait_group 0;" ::: "memory")

// ---------------------------------------------------------------------------
// mega_kernel: all independent preprocessing + output_g as block ranges.
__global__ __launch_bounds__(256) void mega_kernel(
    const float* __restrict__ dq, const float* __restrict__ dk,
    const float* __restrict__ queue_d, const float* __restrict__ featk,
    const float* __restrict__ featq,
    const float* __restrict__ gq, const float* __restrict__ gk,
    const float* __restrict__ queue_g, float* __restrict__ out) {
    __shared__ float buf[4416];
    const int bx = blockIdx.x;
    const int tid = threadIdx.x;

    if (bx < 512) {
        // ---- normt ----
        const int which = bx >> 8;
        const int rr = bx & 255;
        const int b = rr >> 5;
        const int s0 = (rr & 31) * 32;
        const float* src = which ? dk : dq;
        float* dst = which ? g_dkt : g_dqt;
        float (*sm)[129] = reinterpret_cast<float (*)[129]>(buf);
        float (*red)[32] = reinterpret_cast<float (*)[32]>(buf + 4128);
        float* sinv = buf + 4384;
#pragma unroll
        for (int k = 0; k < 16; k++) {
            int idx = tid + k * 256;
            int d = idx >> 5, sl = idx & 31;
            sm[sl][d] = src[((size_t)b * D_ + d) * S_ + s0 + sl];
        }
        __syncthreads();
        {
            int sl = tid & 31, pp = tid >> 5;
            float ss = 0.0f;
#pragma unroll
            for (int d = pp * 16; d < pp * 16 + 16; d++) ss += sm[sl][d] * sm[sl][d];
            red[pp][sl] = ss;
        }
        __syncthreads();
        if (tid < 32) {
            float tot = 0.0f;
#pragma unroll
            for (int p = 0; p < 8; p++) tot += red[p][tid];
            sinv[tid] = rsqrtf(fmaxf(tot, 1e-24f));
        }
        __syncthreads();
#pragma unroll
        for (int k = 0; k < 16; k++) {
            int idx = tid + k * 256;
            int sl = idx >> 7, d = idx & 127;
            dst[((size_t)b * S_ + s0 + sl) * D_ + d] = sm[sl][d] * sinv[sl];
        }
    } else if (bx < 1024) {
        // ---- qconv ----
        const int q0 = (bx - 512) * 32;
        float (*sm)[129] = reinterpret_cast<float (*)[129]>(buf);
#pragma unroll
        for (int k = 0; k < 16; k++) {
            int idx = tid + k * 256;
            int d = idx >> 5, ql = idx & 31;
            sm[ql][d] = queue_d[(size_t)d * K_ + q0 + ql];
        }
        __syncthreads();
        uint2* qt2 = (uint2*)g_qt4;
        const int qt = q0 >> 7;
#pragma unroll
        for (int k = 0; k < 4; k++) {
            int idx = tid + k * 256;
            int ql = idx >> 5, dg = idx & 31;
            __half h[4];
#pragma unroll
            for (int e = 0; e < 4; e++) h[e] = __float2half(sm[ql][dg * 4 + e]);
            int row = (q0 + ql) & 127;
            uint2 packed;
            memcpy(&packed, h, 8);
            qt2[((size_t)(qt * 128 + row)) * 32 + dg] = packed;
        }
    } else if (bx < 1152) {
        // ---- fknorm ----
        const int r = bx - 1024;
        const int b = r >> 4;
        const int s = (r & 15) * 64 + (tid & 63);
        const int g = tid >> 6;
        float (*red)[64] = reinterpret_cast<float (*)[64]>(buf);
        const float* p = featk + (size_t)b * C_ * S_ + s;
        float ss = 0.0f;
#pragma unroll 8
        for (int c = g * 128; c < g * 128 + 128; c++) {
            float v = p[(size_t)c * S_];
            ss += v * v;
        }
        red[g][tid & 63] = ss;
        __syncthreads();
        if (g == 0) {
            float tot = red[0][tid] + red[1][tid] + red[2][tid] + red[3][tid];
            g_fkinv[b * S_ + s] = rsqrtf(fmaxf(tot, 1e-24f));
        }
    } else if (bx < 9344) {
        // ---- fsplit: transpose [b][c][s] -> [b][s][c], fp16 ----
        const int r = bx - 1152;
        const int z = r / 512;
        const int rem = r & 511;
        const int s0 = (rem & 31) * 32;
        const int c0 = (rem >> 5) * 32;
        const bool isk = z < 8;
        const int b = isk ? z : z - 8;
        const float* src = isk ? featk : featq;
        __half* dh = isk ? g_fkh : g_fqh;
        float (*tile)[33] = reinterpret_cast<float (*)[33]>(buf);
        const int tx = tid & 31, ty = tid >> 5;
#pragma unroll
        for (int rr = 0; rr < 4; rr++) {
            int c = c0 + ty * 4 + rr;
            tile[ty * 4 + rr][tx] = src[((size_t)b * C_ + c) * S_ + s0 + tx];
        }
        __syncthreads();
#pragma unroll
        for (int rr = 0; rr < 4; rr++) {
            int s = s0 + ty * 4 + rr;
            dh[((size_t)b * S_ + s) * C_ + c0 + tx] =
                __float2half(tile[tx][ty * 4 + rr]);
        }
    } else {
        // ---- outg ----
        const int r = bx - 9344;
        const int b = r >> 6;
        const int k = (r & 63) * 256 + tid;
        float v = 0.0f;
        if (tid < 128) v = gq[b * D_ + tid];
        buf[tid] = v * v;
        if (tid >= 128) buf[tid] = 0.0f;
        __syncthreads();
        for (int off = 128; off; off >>= 1) {
            if (tid < off) buf[tid] += buf[tid + off];
            __syncthreads();
        }
        float qsc = rsqrtf(fmaxf(buf[0], 1e-24f));
        __syncthreads();
        if (tid < 128) buf[256 + tid] = v * qsc;
        __syncthreads();
        float acc = 0.0f;
#pragma unroll 16
        for (int d = 0; d < D_; d++) acc += buf[256 + d] * queue_g[(size_t)d * K_ + k];
        out[OG + (size_t)b * (K_ + 1) + 1 + k] = acc * INV_TAU;
        if ((r & 63) == 0) {
            float w = 0.0f;
            if (tid < 128) w = gk[b * D_ + tid];
            buf[tid] = w * w;
            if (tid >= 128) buf[tid] = 0.0f;
            __syncthreads();
            for (int off = 128; off; off >>= 1) {
                if (tid < off) buf[tid] += buf[tid + off];
                __syncthreads();
            }
            float ksc = rsqrtf(fmaxf(buf[0], 1e-24f));
            __syncthreads();
            buf[tid] = (tid < 128) ? buf[256 + tid] * w * ksc : 0.0f;
            __syncthreads();
            for (int off = 128; off; off >>= 1) {
                if (tid < off) buf[tid] += buf[tid + off];
                __syncthreads();
            }
            if (tid == 0) {
                out[OG + (size_t)b * (K_ + 1)] = buf[0] * INV_TAU;
                out[TG + b] = 0.0f;
            }
        }
    }
}

// ---------------------------------------------------------------------------
// cosine: CTA = 128i x 64j, 8 warps (2 wm x 4 wn), warp tile 64x16.
// k-chunk 64 per stage (8 stages, half the barriers), streaming pointers,
// top-2 epilogue. Row stride 144B (128B data + 16B pad, conflict-free).
constexpr int XSTRIDE = 144;
constexpr int STG_A_SZ = 128 * XSTRIDE;     // 18432
constexpr int STG_B_SZ = 64 * XSTRIDE;      // 9216
constexpr int STG_BYTES = STG_A_SZ + STG_B_SZ;  // 27648
constexpr int SMEM_COS = 2 * STG_BYTES;     // 55296

__global__ __launch_bounds__(256, 2) void cos_mma_kernel() {
    extern __shared__ char smem[];
    __shared__ u32 smtop[2][4][16][2];
    __shared__ float sinv[128];
    const uint32_t sb = smem_to_u32(smem);
    const int tid = threadIdx.x;
    const int lane = tid & 31;
    const int wid = tid >> 5;
    const int wm = wid & 1;
    const int wn = wid >> 1;
    const int it = blockIdx.x, jt = blockIdx.y, b = blockIdx.z;
    const int i0 = it * 128, j0 = jt * 64;

    if (tid < 128) sinv[tid] = g_fkinv[b * S_ + i0 + tid];

    uint32_t aoff[4], boff;
    {
        int arow = wm * 64 + ((lane >> 3) & 1) * 8 + (lane & 7);
        int acol = ((lane >> 4) & 1) * 16;
#pragma unroll
        for (int i = 0; i < 4; i++) aoff[i] = (arow + i * 16) * XSTRIDE + acol;
        int jsel = (lane >> 4) & 1;
        int kh = (lane >> 3) & 1;
        int brow = lane & 7;
        boff = (wn * 16 + jsel * 8 + brow) * XSTRIDE + kh * 16;
    }

    // streaming pointers: 6 CP16 per thread per stage (1536 total), src
    // advances 64 halfs per kc.
    const __half* srcp[6];
    uint32_t dsto[6];
    {
#pragma unroll
        for (int k = 0; k < 6; k++) {
            int idx = tid + k * 256;
            bool isA = idx < 1024;
            int rem = isA ? idx : idx - 1024;
            int r = rem >> 3;
            int quad = rem & 7;
            int row = isA ? (i0 + r) : (j0 + r);
            srcp[k] = (isA ? g_fkh : g_fqh) +
                      ((size_t)(b * 1024 + row) * 512 + quad * 8);
            dsto[k] = (isA ? 0u : (u32)STG_A_SZ) + r * XSTRIDE + quad * 16;
        }
    }
    auto load_stage = [&](int st, int kc) {
        uint32_t base = sb + st * STG_BYTES;
        int koff = kc * 64;
#pragma unroll
        for (int k = 0; k < 6; k++) CP16(base + dsto[k], srcp[k] + koff);
    };

    float acc[4][2][4];
#pragma unroll
    for (int i = 0; i < 4; i++)
#pragma unroll
        for (int j = 0; j < 2; j++)
#pragma unroll
            for (int r = 0; r < 4; r++) acc[i][j][r] = 0.0f;

    load_stage(0, 0);
    CP_COMMIT();
    CP_WAIT0();
    __syncthreads();

    for (int kc = 0; kc < 8; kc++) {
        const int st = kc & 1;
        if (kc < 7) { load_stage(st ^ 1, kc + 1); CP_COMMIT(); }
        const uint32_t base = sb + st * STG_BYTES;
#pragma unroll
        for (int kh = 0; kh < 4; kh++) {
            uint32_t Af[4][4], Bf[2][2];
#pragma unroll
            for (int i = 0; i < 4; i++)
                LDSM_X4(Af[i][0], Af[i][1], Af[i][2], Af[i][3],
                        base + aoff[i] + kh * 32);
            LDSM_X4(Bf[0][0], Bf[0][1], Bf[1][0], Bf[1][1],
                    base + STG_A_SZ + boff + kh * 32);
#pragma unroll
            for (int i = 0; i < 4; i++)
#pragma unroll
                for (int j = 0; j < 2; j++)
                    MMA_FP16(acc[i][j], Af[i], Bf[j]);
        }
        if (kc < 7) CP_WAIT0();
        __syncthreads();
    }

    float sA[4], sB[4];
#pragma unroll
    for (int i = 0; i < 4; i++) {
        int rl = wm * 64 + i * 16 + (lane >> 2);
        sA[i] = sinv[rl];
        sB[i] = sinv[rl + 8];
    }

    // top-2 over this CTA's 128 i per column j (scaled values)
#pragma unroll
    for (int jf = 0; jf < 2; jf++) {
#pragma unroll
        for (int dj = 0; dj < 2; dj++) {
            u32 t0 = 0, t1 = 0;
#pragma unroll
            for (int i = 0; i < 4; i++) {
                unsigned ig = (unsigned)(i0 + wm * 64 + i * 16 + (lane >> 2));
                ins2(t0, t1, mkkey(acc[i][jf][dj] * sA[i], ig));
                ins2(t0, t1, mkkey(acc[i][jf][dj + 2] * sB[i], ig + 8));
            }
#pragma unroll
            for (int m = 4; m <= 16; m <<= 1) {
                u32 o0 = __shfl_xor_sync(0xFFFFFFFFu, t0, m);
                u32 o1 = __shfl_xor_sync(0xFFFFFFFFu, t1, m);
                ins2(t0, t1, o0);
                ins2(t0, t1, o1);
            }
            if (lane < 4) {
                int j = jf * 8 + 2 * lane + dj;
                smtop[wm][wn][j][0] = t0;
                smtop[wm][wn][j][1] = t1;
            }
        }
    }
    __syncthreads();
    if (tid < 64) {
        int wn2 = tid >> 4, j = tid & 15;
        u32 t0 = smtop[0][wn2][j][0], t1 = smtop[0][wn2][j][1];
        ins2(t0, t1, smtop[1][wn2][j][0]);
        ins2(t0, t1, smtop[1][wn2][j][1]);
        size_t col = (size_t)b * 1024 + j0 + wn2 * 16 + j;
        g_top2[col * 16 + it * 2] = t0;
        g_top2[col * 16 + it * 2 + 1] = t1;
    }
}

// ---------------------------------------------------------------------------
// fingather: warp per column. Exact argmax (lanes 0..15 hold keys) then
// gather matched row: pos_d, B-tile, output_d row0, target_d.
__global__ void fingather_kernel(const float* __restrict__ featq,
                                 const float* __restrict__ featk,
                                 float* __restrict__ out) {
    int col = blockIdx.x * 8 + (threadIdx.x >> 5);
    int lane = threadIdx.x & 31;
    int b = col >> 10, z = col & 1023;
    u32 key = (lane < 16) ? g_top2[(size_t)col * 16 + lane] : 0u;
    u32 m = key;
#pragma unroll
    for (int off = 16; off; off >>= 1)
        m = max(m, __shfl_xor_sync(0xFFFFFFFFu, m, off));
    float vmax = keyval(m);
    bool pass = keyval(key) >= vmax - MARGIN;
    unsigned mask = __ballot_sync(0xFFFFFFFFu, pass);
    u32 best = m;
    if (__popc(mask) > 1) {
        float bv = -1e30f;
        int bi = 0x7FFFFFFF;
        unsigned rem = mask;
        while (rem) {
            int c = __ffs(rem) - 1;
            rem &= rem - 1;
            int i = keyidx(__shfl_sync(0xFFFFFFFFu, key, c));
            const float* fkp = featk + (size_t)b * C_ * S_ + i;
            const float* fqp = featq + (size_t)b * C_ * S_ + z;
            float ex = 0.0f;
#pragma unroll 4
            for (int c0 = lane; c0 < C_; c0 += 32)
                ex += fkp[(size_t)c0 * S_] * fqp[(size_t)c0 * S_];
#pragma unroll
            for (int off = 16; off; off >>= 1)
                ex += __shfl_xor_sync(0xFFFFFFFFu, ex, off);
            ex *= g_fkinv[b * S_ + i];
            if (ex > bv || (ex == bv && i < bi)) { bv = ex; bi = i; }
        }
        best = mkkey(bv, (unsigned)bi);
    }
    int midx = keyidx(best);
    float4 x = ((const float4*)(g_dqt + ((size_t)b * S_ + midx) * D_))[lane];
    float4 y = ((const float4*)(g_dkt + ((size_t)b * S_ + z) * D_))[lane];
    float d = x.x * y.x + x.y * y.y + x.z * y.z + x.w * y.w;
#pragma unroll
    for (int off = 16; off; off >>= 1) d += __shfl_xor_sync(0xFFFFFFFFu, d, off);
    __half h[4] = {__float2half(x.x), __float2half(x.y),
                   __float2half(x.z), __float2half(x.w)};
    uint2 packed;
    memcpy(&packed, h, 8);
    ((uint2*)g_bt4)[((size_t)((b * 8 + (z >> 7)) * 128 + (z & 127))) * 32 + lane] =
        packed;
    if (lane == 0) out[OD + (size_t)b * (K_ + 1) * S_ + z] = d * INV_TAU;
    if (lane == 1) out[TD + b * S_ + z] = 0.0f;
}

// ---------------------------------------------------------------------------
// negd: CTA = 128q x 128z, 4 warps, warp tile 64x64, 8 z-iters (R11 config).
constexpr int TSTRIDE = 272;
constexpr int TILE_SM = 128 * TSTRIDE;
constexpr int SM_A = 0;
constexpr int SM_B = TILE_SM;
constexpr int SMEM_NEGD = 3 * TILE_SM;             // 104448 -> 2 CTAs/SM

__device__ __forceinline__ void cp_tile128(uint32_t smDst, const uint4* src, int tid) {
#pragma unroll
    for (int k = 0; k < 16; k++) {
        int idx = tid + k * 128;
        int row = idx >> 4, w = idx & 15;
        CP16(smDst + row * TSTRIDE + w * 16, src + idx);
    }
}

__global__ __launch_bounds__(128, 2) void negd_mma_kernel(float* __restrict__ out) {
    extern __shared__ char smem[];
    const uint32_t sb = smem_to_u32(smem);
    const int tid = threadIdx.x;
    const int lane = tid & 31;
    const int wid = tid >> 5;
    const int wm = wid & 1;        // 64 q-rows
    const int wn = wid >> 1;       // 64 z-cols
    const int qt = blockIdx.x;
    const int b = blockIdx.y;
    const int q0 = qt << 7;

    uint32_t aoff[4], b4off[4];
    {
        int arow = wm * 64 + ((lane >> 3) & 1) * 8 + (lane & 7);
        int acol = ((lane >> 4) & 1) * 16;
#pragma unroll
        for (int i = 0; i < 4; i++) aoff[i] = (arow + i * 16) * TSTRIDE + acol;
        int jsel = (lane >> 4) & 1;
        int kh = (lane >> 3) & 1;
        int brow = lane & 7;
#pragma unroll
        for (int jp = 0; jp < 4; jp++)
            b4off[jp] = (wn * 64 + (jp * 2 + jsel) * 8 + brow) * TSTRIDE + kh * 16;
    }

    cp_tile128(sb + SM_A, g_qt4 + (size_t)qt * 2048, tid);
    cp_tile128(sb + SM_B, g_bt4 + (size_t)(b * 8) * 2048, tid);
    CP_COMMIT();
    CP_WAIT0();
    __syncthreads();

    for (int zt = 0; zt < 8; zt++) {
        const int stage = zt & 1;
        if (zt < 7) {
            cp_tile128(sb + SM_B + (stage ^ 1) * TILE_SM,
                       g_bt4 + (size_t)(b * 8 + zt + 1) * 2048, tid);
            CP_COMMIT();
        }

        float acc[4][8][4];
#pragma unroll
        for (int i = 0; i < 4; i++)
#pragma unroll
            for (int j = 0; j < 8; j++)
#pragma unroll
                for (int r = 0; r < 4; r++) acc[i][j][r] = 0.0f;

        const uint32_t aB = sb + SM_A;
        const uint32_t bB = sb + SM_B + stage * TILE_SM;

#pragma unroll
        for (int ks = 0; ks < 8; ks++) {
            uint32_t Af[4][4], Bf[8][2];
#pragma unroll
            for (int i = 0; i < 4; i++)
                LDSM_X4(Af[i][0], Af[i][1], Af[i][2], Af[i][3], aB + aoff[i] + ks * 32);
#pragma unroll
            for (int jp = 0; jp < 4; jp++)
                LDSM_X4(Bf[jp * 2][0], Bf[jp * 2][1], Bf[jp * 2 + 1][0], Bf[jp * 2 + 1][1],
                        bB + b4off[jp] + ks * 32);
#pragma unroll
            for (int i = 0; i < 4; i++)
#pragma unroll
                for (int j = 0; j < 8; j++)
                    MMA_FP16(acc[i][j], Af[i], Bf[j]);
        }

#pragma unroll
        for (int i = 0; i < 4; i++) {
            int q = q0 + wm * 64 + i * 16 + (lane >> 2);
            float* rowp = out + OD + (size_t)(b * (K_ + 1) + 1 + q) * S_;
#pragma unroll
            for (int j = 0; j < 8; j++) {
                int z = zt * 128 + wn * 64 + j * 8 + 2 * (lane & 3);
                float2 w0 = {acc[i][j][0] * INV_TAU, acc[i][j][1] * INV_TAU};
                float2 w1 = {acc[i][j][2] * INV_TAU, acc[i][j][3] * INV_TAU};
                *reinterpret_cast<float2*>(rowp + z) = w0;
                *reinterpret_cast<float2*>(rowp + 8 * S_ + z) = w1;
            }
        }

        if (zt < 7) CP_WAIT0();
        __syncthreads();
    }
}

// ---------------------------------------------------------------------------
extern "C" void kernel_launch(void* const* d_in, const int* in_sizes, int n_in,
                              void* d_out, int out_size) {
    const float* g_q     = (const float*)d_in[0];
    const float* g_k     = (const float*)d_in[1];
    const float* d_q     = (const float*)d_in[2];
    const float* d_k     = (const float*)d_in[3];
    const float* feat_q  = (const float*)d_in[4];
    const float* feat_k  = (const float*)d_in[5];
    const float* queue_g = (const float*)d_in[6];
    const float* queue_d = (const float*)d_in[7];
    float* out = (float*)d_out;

    cudaFuncSetAttribute(negd_mma_kernel,
                         cudaFuncAttributeMaxDynamicSharedMemorySize, SMEM_NEGD);
    cudaFuncSetAttribute(cos_mma_kernel,
                         cudaFuncAttributeMaxDynamicSharedMemorySize, SMEM_COS);

    mega_kernel<<<9856, 256>>>(d_q, d_k, queue_d, feat_k, feat_q,
                               g_q, g_k, queue_g, out);                 // 0
    cos_mma_kernel<<<dim3(8, 16, B_), 256, SMEM_COS>>>();               // 1
    fingather_kernel<<<1024, 256>>>(feat_q, feat_k, out);               // 2
    negd_mma_kernel<<<dim3(128, B_), 128, SMEM_NEGD>>>(out);            // 3
}